// round 12
// baseline (speedup 1.0000x reference)
#include <cuda_runtime.h>
#include <cuda_fp16.h>
#include <math.h>

#define NMAX 100000
#define EMAX 1600000
#define HEADS 4
#define HID 32
#define F1 128
#define IN_NODE 12
#define IN_GLB 11
#define IN1 23
#define EDGE_DIM 5
#define DEC_IN 69
#define DEC_H1 64
#define DEC_H2 32
#define DEC_OUT 4

typedef unsigned long long ull;

__device__ __align__(16) __half g_gh[NMAX * F1];
__device__ float g_h1[NMAX * F1];
__device__ float g_h2[NMAX * HID];
__device__ __align__(16) __half g_pah[NMAX * DEC_H1];
__device__ __align__(16) __half g_pbh[NMAX * DEC_H1];
__device__ __align__(16) float g_als[NMAX * HEADS];
__device__ __align__(16) float g_ald[NMAX * HEADS];
__device__ int   g_cnt[NMAX];
__device__ int   g_off[NMAX + 1];
__device__ int   g_cur[NMAX];
__device__ int   g_srcs[EMAX];
__device__ int   g_bsum[128];
__device__ float g_t1[F1];
__device__ float g_w1tt[IN_NODE * F1];
__device__ float g_w2t[DEC_H1 * DEC_H2];
__device__ __align__(16) ull g_w2p[F1 * F1];

__device__ __forceinline__ float lrelu02(float x) { return x > 0.f ? x : 0.2f * x; }
__device__ __forceinline__ float eluf(float x)    { return x > 0.f ? x : expm1f(x); }

__device__ __forceinline__ ull pk2(float lo, float hi) {
    ull r;
    asm("mov.b64 %0, {%1, %2};" : "=l"(r) : "f"(lo), "f"(hi));
    return r;
}
__device__ __forceinline__ void fma2(ull& d, ull a, ull b) {
    asm("fma.rn.f32x2 %0, %1, %2, %0;" : "+l"(d) : "l"(a), "l"(b));
}
__device__ __forceinline__ float2 upk2(ull v) {
    float2 f;
    asm("mov.b64 {%0, %1}, %2;" : "=f"(f.x), "=f"(f.y) : "l"(v));
    return f;
}

// ---------------- merged prep: zero cnt + t1/w1tt/w2t + w2p -----------------
__global__ void k_prep_all(const float* __restrict__ u, const float* __restrict__ W1,
                           const float* __restrict__ dw2, const float* __restrict__ W2,
                           int N) {
    int b = blockIdx.x;
    int tid = threadIdx.x;
    if (b < 64) {                         // w2p: 64 blocks x 256 = 16384
        int i = b * 256 + tid;
        int k = i >> 7, f = i & 127;
        float w = W2[f * F1 + k];
        g_w2p[i] = pk2(w, w);
    } else if (b == 64) {                 // t1, w1tt, w2t
        if (tid < F1) {
            float s = 0.f;
            #pragma unroll
            for (int k = 0; k < IN_GLB; k++) s += u[k] * W1[tid * IN1 + IN_NODE + k];
            g_t1[tid] = s;
        }
        for (int i = tid; i < IN_NODE * F1; i += 256) {
            int k = i >> 7, f = i & 127;
            g_w1tt[i] = W1[f * IN1 + k];
        }
        for (int i = tid; i < DEC_H1 * DEC_H2; i += 256) {
            int k = i >> 5, o = i & 31;
            g_w2t[i] = dw2[o * DEC_H1 + k];
        }
    } else {                              // zero cnt
        int i = (b - 65) * 256 + tid;
        if (i < N) g_cnt[i] = 0;
    }
}

// ---------------- layer-1 node transform + attention logits ----------------
__global__ void k_gemm1(const float* __restrict__ x,
                        const float* __restrict__ asrc, const float* __restrict__ adst,
                        int N) {
    int n0 = blockIdx.x * 4;
    int f = threadIdx.x;
    __shared__ float xs[4][IN_NODE];
    if (f < 4 * IN_NODE) {
        int i = f / IN_NODE, k = f - i * IN_NODE;
        int n = n0 + i;
        xs[i][k] = (n < N) ? __ldcs(&x[n * IN_NODE + k]) : 0.f;
    }
    __syncthreads();
    float acc[4];
    float t = g_t1[f];
    #pragma unroll
    for (int i = 0; i < 4; i++) acc[i] = t;
    #pragma unroll
    for (int k = 0; k < IN_NODE; k++) {
        float w = g_w1tt[k * F1 + f];
        #pragma unroll
        for (int i = 0; i < 4; i++) acc[i] += xs[i][k] * w;
    }
    int h = f >> 5;
    float cas = asrc[f], cad = adst[f];
    #pragma unroll
    for (int i = 0; i < 4; i++) {
        int n = n0 + i;
        if (n >= N) break;
        g_gh[n * F1 + f] = __float2half_rn(acc[i]);
        float vs = acc[i] * cas, vd = acc[i] * cad;
        #pragma unroll
        for (int o = 16; o; o >>= 1) {
            vs += __shfl_xor_sync(0xffffffffu, vs, o);
            vd += __shfl_xor_sync(0xffffffffu, vd, o);
        }
        if ((f & 31) == 0) {
            g_als[n * HEADS + h] = vs;
            g_ald[n * HEADS + h] = vd;
        }
    }
}

// ---------------- layer-2 node transform: 32 nodes/block, 4f x 8n tiles -----
#define G2N 32
#define HSTS 36
__global__ __launch_bounds__(128) void k_gemm2(const float* __restrict__ asrc,
                                               const float* __restrict__ adst,
                                               int N) {
    __shared__ __align__(16) float hst[F1 * HSTS];
    int tid = threadIdx.x;
    int n0 = blockIdx.x * G2N;

    for (int i = tid; i < G2N * (F1 / 4); i += 128) {
        int n = i >> 5, f4 = i & 31;
        float4 hv = make_float4(0.f, 0.f, 0.f, 0.f);
        if (n0 + n < N)
            hv = __ldcs(reinterpret_cast<const float4*>(&g_h1[(size_t)(n0 + n) * F1 + 4 * f4]));
        hst[(4 * f4 + 0) * HSTS + n] = hv.x;
        hst[(4 * f4 + 1) * HSTS + n] = hv.y;
        hst[(4 * f4 + 2) * HSTS + n] = hv.z;
        hst[(4 * f4 + 3) * HSTS + n] = hv.w;
    }
    __syncthreads();

    int fq = tid >> 2, nq = tid & 3;
    int f0 = fq * 4, nn0 = nq * 8;

    ull acc[4][4];
    #pragma unroll
    for (int a = 0; a < 4; a++)
        #pragma unroll
        for (int b = 0; b < 4; b++) acc[a][b] = 0ull;

    #pragma unroll 4
    for (int k = 0; k < F1; k++) {
        ulonglong2 h01 = *reinterpret_cast<const ulonglong2*>(&hst[k * HSTS + nn0]);
        ulonglong2 h23 = *reinterpret_cast<const ulonglong2*>(&hst[k * HSTS + nn0 + 4]);
        const ulonglong2* wp = reinterpret_cast<const ulonglong2*>(&g_w2p[(size_t)k * F1 + f0]);
        ulonglong2 w01 = wp[0];
        ulonglong2 w23 = wp[1];
        fma2(acc[0][0], h01.x, w01.x); fma2(acc[0][1], h01.y, w01.x);
        fma2(acc[0][2], h23.x, w01.x); fma2(acc[0][3], h23.y, w01.x);
        fma2(acc[1][0], h01.x, w01.y); fma2(acc[1][1], h01.y, w01.y);
        fma2(acc[1][2], h23.x, w01.y); fma2(acc[1][3], h23.y, w01.y);
        fma2(acc[2][0], h01.x, w23.x); fma2(acc[2][1], h01.y, w23.x);
        fma2(acc[2][2], h23.x, w23.x); fma2(acc[2][3], h23.y, w23.x);
        fma2(acc[3][0], h01.x, w23.y); fma2(acc[3][1], h01.y, w23.y);
        fma2(acc[3][2], h23.x, w23.y); fma2(acc[3][3], h23.y, w23.y);
    }

    float av[4][8];
    #pragma unroll
    for (int f = 0; f < 4; f++)
        #pragma unroll
        for (int p = 0; p < 4; p++) {
            float2 t = upk2(acc[f][p]);
            av[f][2 * p] = t.x;
            av[f][2 * p + 1] = t.y;
        }

    float4 cas = *reinterpret_cast<const float4*>(&asrc[f0]);
    float4 cad = *reinterpret_cast<const float4*>(&adst[f0]);
    float vs[8], vd[8];
    #pragma unroll
    for (int j = 0; j < 8; j++) {
        int n = n0 + nn0 + j;
        if (n < N) {
            __half2 p0 = __floats2half2_rn(av[0][j], av[1][j]);
            __half2 p1 = __floats2half2_rn(av[2][j], av[3][j]);
            __half2* gp = reinterpret_cast<__half2*>(&g_gh[(size_t)n * F1 + f0]);
            gp[0] = p0;
            gp[1] = p1;
        }
        vs[j] = av[0][j] * cas.x + av[1][j] * cas.y + av[2][j] * cas.z + av[3][j] * cas.w;
        vd[j] = av[0][j] * cad.x + av[1][j] * cad.y + av[2][j] * cad.z + av[3][j] * cad.w;
    }
    #pragma unroll
    for (int j = 0; j < 8; j++) {
        #pragma unroll
        for (int m = 4; m <= 16; m <<= 1) {
            vs[j] += __shfl_xor_sync(0xffffffffu, vs[j], m);
            vd[j] += __shfl_xor_sync(0xffffffffu, vd[j], m);
        }
    }
    if ((tid & 28) == 0) {
        int h = tid >> 5;
        #pragma unroll
        for (int j = 0; j < 8; j++) {
            int n = n0 + nn0 + j;
            if (n < N) {
                g_als[n * HEADS + h] = vs[j];
                g_ald[n * HEADS + h] = vd[j];
            }
        }
    }
}

// ---------------- CSR build --------------------------------------------------
__global__ void k_hist(const int* __restrict__ dst, int M) {
    int e = blockIdx.x * blockDim.x + threadIdx.x;
    if (e < M) atomicAdd(&g_cnt[__ldcs(&dst[e])], 1);
}
__global__ void k_scan1(int N) {
    __shared__ int sh[1024];
    int tid = threadIdx.x;
    int i = blockIdx.x * 1024 + tid;
    int v = (i < N) ? g_cnt[i] : 0;
    sh[tid] = v;
    __syncthreads();
    for (int o = 1; o < 1024; o <<= 1) {
        int t = (tid >= o) ? sh[tid - o] : 0;
        __syncthreads();
        sh[tid] += t;
        __syncthreads();
    }
    if (i < N) g_off[i] = sh[tid] - v;
    if (tid == 1023) g_bsum[blockIdx.x] = sh[1023];
}
__global__ void k_scan3(int nb, int N, int M) {
    __shared__ int sh[128];
    int tid = threadIdx.x;
    if (tid < 128) {
        int v = (tid < nb) ? g_bsum[tid] : 0;
        sh[tid] = v;
    }
    __syncthreads();
    if (tid < 128) {
        for (int o = 1; o < 128; o <<= 1) {
            int t = (tid >= o) ? sh[tid - o] : 0;
            __syncthreads();
            sh[tid] += t;
            __syncthreads();
        }
    } else {
        for (int o = 1; o < 128; o <<= 1) { __syncthreads(); __syncthreads(); }
    }
    int i = blockIdx.x * blockDim.x + tid;
    if (i < N) {
        int blk = i >> 10;
        int ex = (blk == 0) ? 0 : sh[blk - 1];
        int v = g_off[i] + ex;
        g_off[i] = v;
        g_cur[i] = v;
    }
    if (i == 0) g_off[N] = M;
}
__global__ void k_scatter(const int* __restrict__ src, const int* __restrict__ dst, int M) {
    int e = blockIdx.x * blockDim.x + threadIdx.x;
    if (e < M) {
        int d = __ldcs(&dst[e]);
        int p = atomicAdd(&g_cur[d], 1);
        g_srcs[p] = __ldcs(&src[e]);
    }
}

// ---------------- GAT aggregation (4 warps/node; fp16 gathers) --------------
__global__ void k_agg(const float* __restrict__ bias, int concat, int N) {
    int n = blockIdx.x;
    if (n >= N) return;
    int h = threadIdx.x >> 5;
    int lane = threadIdx.x & 31;
    int beg = g_off[n], end = g_off[n + 1];

    float ad = g_ald[n * HEADS + h];
    float ws = __expf(lrelu02(g_als[n * HEADS + h] + ad));

    const __half* gg = g_gh + (h << 5) + lane;
    float acc = ws * __half2float(gg[(size_t)n * F1]);
    float psum = 0.f;
    for (int base = beg; base < end; base += 32) {
        int j = base + lane;
        float w = 0.f;
        int s = 0;
        if (j < end) {
            s = g_srcs[j];
            w = __expf(lrelu02(g_als[s * HEADS + h] + ad));
            psum += w;
        }
        int lim = min(32, end - base);
        int kk = 0;
        for (; kk + 4 <= lim; kk += 4) {
            float w0 = __shfl_sync(0xffffffffu, w, kk);
            float w1 = __shfl_sync(0xffffffffu, w, kk + 1);
            float w2 = __shfl_sync(0xffffffffu, w, kk + 2);
            float w3 = __shfl_sync(0xffffffffu, w, kk + 3);
            int s0 = __shfl_sync(0xffffffffu, s, kk);
            int s1 = __shfl_sync(0xffffffffu, s, kk + 1);
            int s2 = __shfl_sync(0xffffffffu, s, kk + 2);
            int s3 = __shfl_sync(0xffffffffu, s, kk + 3);
            float v0 = __half2float(gg[(size_t)s0 * F1]);
            float v1 = __half2float(gg[(size_t)s1 * F1]);
            float v2 = __half2float(gg[(size_t)s2 * F1]);
            float v3 = __half2float(gg[(size_t)s3 * F1]);
            acc += w0 * v0;
            acc += w1 * v1;
            acc += w2 * v2;
            acc += w3 * v3;
        }
        for (; kk < lim; kk++) {
            float wk = __shfl_sync(0xffffffffu, w, kk);
            int sk = __shfl_sync(0xffffffffu, s, kk);
            acc += wk * __half2float(gg[(size_t)sk * F1]);
        }
    }
    #pragma unroll
    for (int o = 16; o; o >>= 1) psum += __shfl_xor_sync(0xffffffffu, psum, o);
    float v = acc / (psum + ws);

    if (concat) {
        v += bias[(h << 5) + lane];
        __stcs(&g_h1[n * F1 + (h << 5) + lane], eluf(v));
    } else {
        __shared__ float sm[F1];
        sm[(h << 5) + lane] = v;
        __syncthreads();
        if (h == 0) {
            float t = (sm[lane] + sm[32 + lane] + sm[64 + lane] + sm[96 + lane]) * 0.25f
                      + bias[lane];
            g_h2[n * HID + lane] = eluf(t);
        }
    }
}

// ---------------- decoder precompute: pa/pb (fp16 out) ----------------------
__global__ __launch_bounds__(256) void k_pab(const float* __restrict__ dw1, int N) {
    __shared__ float sdw[64 * 65];
    __shared__ float sh2[16 * 32];
    int tid = threadIdx.x;
    for (int i = tid; i < 64 * 64; i += 256) {
        int o = i >> 6, k = i & 63;
        sdw[o * 65 + k] = dw1[o * DEC_IN + k];
    }
    int n0 = blockIdx.x * 16;
    for (int i = tid; i < 16 * 32; i += 256) {
        int nl = i >> 5, k = i & 31;
        int n = n0 + nl;
        sh2[i] = (n < N) ? g_h2[n * HID + k] : 0.f;
    }
    __syncthreads();
    int o = tid & 63, ng = tid >> 6;
    float pa[4] = {0.f, 0.f, 0.f, 0.f}, pb[4] = {0.f, 0.f, 0.f, 0.f};
    #pragma unroll
    for (int k = 0; k < 32; k++) {
        float wa = sdw[o * 65 + k];
        float wb = sdw[o * 65 + 32 + k];
        #pragma unroll
        for (int j = 0; j < 4; j++) {
            float hv = sh2[(ng * 4 + j) * 32 + k];
            pa[j] += wa * hv;
            pb[j] += wb * hv;
        }
    }
    #pragma unroll
    for (int j = 0; j < 4; j++) {
        int n = n0 + ng * 4 + j;
        if (n < N) {
            g_pah[n * 64 + o] = __float2half_rn(pa[j]);
            g_pbh[n * 64 + o] = __float2half_rn(pb[j]);
        }
    }
}

// ---------------- decoder: 64-edge tiles; GEMM2 8e x 4o on 64 threads -------
#define TB 64
#define ZS (TB + 4)
__global__ __launch_bounds__(256) void k_dec(
    const int* __restrict__ ei, const float* __restrict__ eattr,
    const float* __restrict__ dw1, const float* __restrict__ db1,
    const float* __restrict__ db2, const float* __restrict__ dw3,
    const float* __restrict__ db3, float* __restrict__ out, int M) {
    __shared__ __align__(16) ull sw2p[DEC_H1 * DEC_H2];
    __shared__ float sw3[DEC_H2 * DEC_OUT];
    __shared__ float sb2[DEC_H2];
    __shared__ float sb3[DEC_OUT];
    __shared__ float sw1c[EDGE_DIM * 64];
    __shared__ float sdb1[64];
    __shared__ int ssrc[TB], sdst[TB];
    __shared__ float eat[TB * EDGE_DIM];
    __shared__ __align__(16) float z1t[DEC_H1 * ZS];
    __shared__ __align__(16) float z2t[DEC_H2 * ZS];
    int tid = threadIdx.x;

    for (int i = tid; i < DEC_H1 * DEC_H2; i += 256) {
        float w = g_w2t[i];
        sw2p[i] = pk2(w, w);
    }
    if (tid < 128) sw3[tid] = dw3[tid];
    if (tid < 64)  sdb1[tid] = db1[tid];
    if (tid < 32)  sb2[tid] = db2[tid];
    if (tid < 4)   sb3[tid] = db3[tid];
    for (int i = tid; i < EDGE_DIM * 64; i += 256) {
        int k = i >> 6, o = i & 63;
        sw1c[i] = dw1[o * DEC_IN + 64 + k];
    }

    const int* srcp = ei;
    const int* dstp = ei + M;
    int ntiles = (M + TB - 1) / TB;
    // GEMM2 mapping (tid < 64): eg = tid&7 (e0 = 8*eg), og = tid>>3 (o0 = 4*og)
    int eg = tid & 7, og = (tid >> 3) & 7;
    int e0 = eg * 8, o0 = og * 4;

    for (int tile = blockIdx.x; tile < ntiles; tile += gridDim.x) {
        int eb = tile * TB;
        int nE = min(TB, M - eb);
        __syncthreads();
        if (tid < TB) {
            ssrc[tid] = (tid < nE) ? __ldcs(&srcp[eb + tid]) : 0;
            sdst[tid] = (tid < nE) ? __ldcs(&dstp[eb + tid]) : 0;
        }
        for (int i = tid; i < TB * EDGE_DIM; i += 256) {
            int gi = eb * EDGE_DIM + i;
            eat[i] = (gi < M * EDGE_DIM) ? __ldcs(&eattr[gi]) : 0.f;
        }
        __syncthreads();

        for (int i = tid; i < TB * 64; i += 256) {
            int e = i >> 6, o = i & 63;
            float v = __half2float(g_pah[(size_t)ssrc[e] * 64 + o])
                    + __half2float(g_pbh[(size_t)sdst[e] * 64 + o])
                    + sdb1[o];
            #pragma unroll
            for (int k = 0; k < EDGE_DIM; k++) v += sw1c[k * 64 + o] * eat[e * EDGE_DIM + k];
            z1t[o * ZS + e] = fmaxf(v, 0.f);
        }
        __syncthreads();

        if (tid < 64) {
            ull acc[4][4];   // [o][e-pair], 8 edges = 4 pairs
            #pragma unroll
            for (int a = 0; a < 4; a++)
                #pragma unroll
                for (int b = 0; b < 4; b++) acc[a][b] = 0ull;
            #pragma unroll 8
            for (int k = 0; k < DEC_H1; k++) {
                ulonglong2 zp0 = *reinterpret_cast<const ulonglong2*>(&z1t[k * ZS + e0]);
                ulonglong2 zp1 = *reinterpret_cast<const ulonglong2*>(&z1t[k * ZS + e0 + 4]);
                ulonglong2 w01 = *reinterpret_cast<const ulonglong2*>(&sw2p[k * DEC_H2 + o0]);
                ulonglong2 w23 = *reinterpret_cast<const ulonglong2*>(&sw2p[k * DEC_H2 + o0 + 2]);
                fma2(acc[0][0], zp0.x, w01.x); fma2(acc[0][1], zp0.y, w01.x);
                fma2(acc[0][2], zp1.x, w01.x); fma2(acc[0][3], zp1.y, w01.x);
                fma2(acc[1][0], zp0.x, w01.y); fma2(acc[1][1], zp0.y, w01.y);
                fma2(acc[1][2], zp1.x, w01.y); fma2(acc[1][3], zp1.y, w01.y);
                fma2(acc[2][0], zp0.x, w23.x); fma2(acc[2][1], zp0.y, w23.x);
                fma2(acc[2][2], zp1.x, w23.x); fma2(acc[2][3], zp1.y, w23.x);
                fma2(acc[3][0], zp0.x, w23.y); fma2(acc[3][1], zp0.y, w23.y);
                fma2(acc[3][2], zp1.x, w23.y); fma2(acc[3][3], zp1.y, w23.y);
            }
            #pragma unroll
            for (int o = 0; o < 4; o++) {
                float b = sb2[o0 + o];
                float2 t0 = upk2(acc[o][0]);
                float2 t1 = upk2(acc[o][1]);
                float2 t2 = upk2(acc[o][2]);
                float2 t3 = upk2(acc[o][3]);
                float4 ov0 = make_float4(fmaxf(t0.x + b, 0.f), fmaxf(t0.y + b, 0.f),
                                         fmaxf(t1.x + b, 0.f), fmaxf(t1.y + b, 0.f));
                float4 ov1 = make_float4(fmaxf(t2.x + b, 0.f), fmaxf(t2.y + b, 0.f),
                                         fmaxf(t3.x + b, 0.f), fmaxf(t3.y + b, 0.f));
                *reinterpret_cast<float4*>(&z2t[(o0 + o) * ZS + e0]) = ov0;
                *reinterpret_cast<float4*>(&z2t[(o0 + o) * ZS + e0 + 4]) = ov1;
            }
        }
        __syncthreads();

        {
            int e = tid & 63, o = tid >> 6;
            float acc = sb3[o];
            #pragma unroll
            for (int k = 0; k < DEC_H2; k++) acc += z2t[k * ZS + e] * sw3[o * DEC_H2 + k];
            if (e < nE) __stcs(&out[(eb + e) * DEC_OUT + o], acc);
        }
    }
}

// ---------------- launch -----------------------------------------------------
extern "C" void kernel_launch(void* const* d_in, const int* in_sizes, int n_in,
                              void* d_out, int out_size) {
    const float* x     = (const float*)d_in[0];
    const int*   ei    = (const int*)d_in[1];
    const float* eattr = (const float*)d_in[2];
    const float* u     = (const float*)d_in[3];
    const float* W1    = (const float*)d_in[4];
    const float* as1   = (const float*)d_in[5];
    const float* ad1   = (const float*)d_in[6];
    const float* b1    = (const float*)d_in[7];
    const float* W2    = (const float*)d_in[8];
    const float* as2   = (const float*)d_in[9];
    const float* ad2   = (const float*)d_in[10];
    const float* b2    = (const float*)d_in[11];
    const float* dw1   = (const float*)d_in[12];
    const float* db1   = (const float*)d_in[13];
    const float* dw2   = (const float*)d_in[14];
    const float* db2   = (const float*)d_in[15];
    const float* dw3   = (const float*)d_in[16];
    const float* db3   = (const float*)d_in[17];
    float* out = (float*)d_out;

    int N = in_sizes[0] / IN_NODE;
    int M = in_sizes[1] / 2;
    if (N > NMAX || M > EMAX || N <= 0 || M <= 0) return;

    const int* srcp = ei;
    const int* dstp = ei + M;
    int nb = (N + 1023) / 1024;

    k_prep_all<<<65 + (N + 255) / 256, 256>>>(u, W1, dw2, W2, N);
    k_hist<<<(M + 255) / 256, 256>>>(dstp, M);
    k_scan1<<<nb, 1024>>>(N);
    k_scan3<<<(N + 255) / 256, 256>>>(nb, N, M);
    k_scatter<<<(M + 255) / 256, 256>>>(srcp, dstp, M);

    k_gemm1<<<(N + 3) / 4, 128>>>(x, as1, ad1, N);
    k_agg<<<N, 128>>>(b1, 1, N);

    k_gemm2<<<(N + G2N - 1) / G2N, 128>>>(as2, ad2, N);
    k_agg<<<N, 128>>>(b2, 0, N);

    k_pab<<<(N + 15) / 16, 256>>>(dw1, N);
    k_dec<<<1184, 256>>>(ei, eattr, dw1, db1, db2, dw3, db3, out, M);
}

// round 13
// speedup vs baseline: 1.2083x; 1.2083x over previous
#include <cuda_runtime.h>
#include <cuda_fp16.h>
#include <math.h>

#define NMAX 100000
#define EMAX 1600000
#define HEADS 4
#define HID 32
#define F1 128
#define IN_NODE 12
#define IN_GLB 11
#define IN1 23
#define EDGE_DIM 5
#define DEC_IN 69
#define DEC_H1 64
#define DEC_H2 32
#define DEC_OUT 4

typedef unsigned long long ull;

__device__ __align__(16) __half g_gh[NMAX * F1];
__device__ float g_h1[NMAX * F1];
__device__ float g_h2[NMAX * HID];
__device__ __align__(16) __half g_pah[NMAX * DEC_H1];
__device__ __align__(16) __half g_pbh[NMAX * DEC_H1];
__device__ __align__(16) float g_als[NMAX * HEADS];
__device__ __align__(16) float g_ald[NMAX * HEADS];
__device__ int   g_cnt[NMAX];
__device__ int   g_off[NMAX + 1];
__device__ int   g_cur[NMAX];
__device__ int   g_srcs[EMAX];
__device__ int   g_bsum[128];
__device__ float g_t1[F1];
__device__ float g_w1tt[IN_NODE * F1];
__device__ float g_w2t[DEC_H1 * DEC_H2];
__device__ __align__(16) ull g_w2p[F1 * F1];

__device__ __forceinline__ float lrelu02(float x) { return x > 0.f ? x : 0.2f * x; }
__device__ __forceinline__ float eluf(float x)    { return x > 0.f ? x : expm1f(x); }

__device__ __forceinline__ ull pk2(float lo, float hi) {
    ull r;
    asm("mov.b64 %0, {%1, %2};" : "=l"(r) : "f"(lo), "f"(hi));
    return r;
}
__device__ __forceinline__ void fma2(ull& d, ull a, ull b) {
    asm("fma.rn.f32x2 %0, %1, %2, %0;" : "+l"(d) : "l"(a), "l"(b));
}
__device__ __forceinline__ float2 upk2(ull v) {
    float2 f;
    asm("mov.b64 {%0, %1}, %2;" : "=f"(f.x), "=f"(f.y) : "l"(v));
    return f;
}

// ---------------- merged prep: zero cnt + t1/w1tt/w2t + w2p -----------------
__global__ void k_prep_all(const float* __restrict__ u, const float* __restrict__ W1,
                           const float* __restrict__ dw2, const float* __restrict__ W2,
                           int N) {
    int b = blockIdx.x;
    int tid = threadIdx.x;
    if (b < 64) {
        int i = b * 256 + tid;
        int k = i >> 7, f = i & 127;
        float w = W2[f * F1 + k];
        g_w2p[i] = pk2(w, w);
    } else if (b == 64) {
        if (tid < F1) {
            float s = 0.f;
            #pragma unroll
            for (int k = 0; k < IN_GLB; k++) s += u[k] * W1[tid * IN1 + IN_NODE + k];
            g_t1[tid] = s;
        }
        for (int i = tid; i < IN_NODE * F1; i += 256) {
            int k = i >> 7, f = i & 127;
            g_w1tt[i] = W1[f * IN1 + k];
        }
        for (int i = tid; i < DEC_H1 * DEC_H2; i += 256) {
            int k = i >> 5, o = i & 31;
            g_w2t[i] = dw2[o * DEC_H1 + k];
        }
    } else {
        int i = (b - 65) * 256 + tid;
        if (i < N) g_cnt[i] = 0;
    }
}

// ---------------- layer-1 node transform (8 nodes/block) --------------------
#define G1N 8
__global__ __launch_bounds__(128) void k_gemm1(const float* __restrict__ x,
                        const float* __restrict__ asrc, const float* __restrict__ adst,
                        int N) {
    int n0 = blockIdx.x * G1N;
    int f = threadIdx.x;
    __shared__ float xs[G1N][IN_NODE];
    if (f < G1N * IN_NODE) {
        int i = f / IN_NODE, k = f - i * IN_NODE;
        int n = n0 + i;
        xs[i][k] = (n < N) ? __ldcs(&x[n * IN_NODE + k]) : 0.f;
    }
    __syncthreads();
    float acc[G1N];
    float t = g_t1[f];
    #pragma unroll
    for (int i = 0; i < G1N; i++) acc[i] = t;
    #pragma unroll
    for (int k = 0; k < IN_NODE; k++) {
        float w = g_w1tt[k * F1 + f];
        #pragma unroll
        for (int i = 0; i < G1N; i++) acc[i] += xs[i][k] * w;
    }
    int h = f >> 5;
    float cas = asrc[f], cad = adst[f];
    #pragma unroll
    for (int i = 0; i < G1N; i++) {
        int n = n0 + i;
        if (n >= N) break;
        g_gh[n * F1 + f] = __float2half_rn(acc[i]);
        float vs = acc[i] * cas, vd = acc[i] * cad;
        #pragma unroll
        for (int o = 16; o; o >>= 1) {
            vs += __shfl_xor_sync(0xffffffffu, vs, o);
            vd += __shfl_xor_sync(0xffffffffu, vd, o);
        }
        if ((f & 31) == 0) {
            g_als[n * HEADS + h] = vs;
            g_ald[n * HEADS + h] = vd;
        }
    }
}

// ---------------- layer-2 node transform: 32 nodes/block, 4f x 8n tiles -----
#define G2N 32
#define HSTS 36
__global__ __launch_bounds__(128) void k_gemm2(const float* __restrict__ asrc,
                                               const float* __restrict__ adst,
                                               int N) {
    __shared__ __align__(16) float hst[F1 * HSTS];
    int tid = threadIdx.x;
    int n0 = blockIdx.x * G2N;

    for (int i = tid; i < G2N * (F1 / 4); i += 128) {
        int n = i >> 5, f4 = i & 31;
        float4 hv = make_float4(0.f, 0.f, 0.f, 0.f);
        if (n0 + n < N)
            hv = __ldcs(reinterpret_cast<const float4*>(&g_h1[(size_t)(n0 + n) * F1 + 4 * f4]));
        hst[(4 * f4 + 0) * HSTS + n] = hv.x;
        hst[(4 * f4 + 1) * HSTS + n] = hv.y;
        hst[(4 * f4 + 2) * HSTS + n] = hv.z;
        hst[(4 * f4 + 3) * HSTS + n] = hv.w;
    }
    __syncthreads();

    int fq = tid >> 2, nq = tid & 3;
    int f0 = fq * 4, nn0 = nq * 8;

    ull acc[4][4];
    #pragma unroll
    for (int a = 0; a < 4; a++)
        #pragma unroll
        for (int b = 0; b < 4; b++) acc[a][b] = 0ull;

    #pragma unroll 4
    for (int k = 0; k < F1; k++) {
        ulonglong2 h01 = *reinterpret_cast<const ulonglong2*>(&hst[k * HSTS + nn0]);
        ulonglong2 h23 = *reinterpret_cast<const ulonglong2*>(&hst[k * HSTS + nn0 + 4]);
        const ulonglong2* wp = reinterpret_cast<const ulonglong2*>(&g_w2p[(size_t)k * F1 + f0]);
        ulonglong2 w01 = wp[0];
        ulonglong2 w23 = wp[1];
        fma2(acc[0][0], h01.x, w01.x); fma2(acc[0][1], h01.y, w01.x);
        fma2(acc[0][2], h23.x, w01.x); fma2(acc[0][3], h23.y, w01.x);
        fma2(acc[1][0], h01.x, w01.y); fma2(acc[1][1], h01.y, w01.y);
        fma2(acc[1][2], h23.x, w01.y); fma2(acc[1][3], h23.y, w01.y);
        fma2(acc[2][0], h01.x, w23.x); fma2(acc[2][1], h01.y, w23.x);
        fma2(acc[2][2], h23.x, w23.x); fma2(acc[2][3], h23.y, w23.x);
        fma2(acc[3][0], h01.x, w23.y); fma2(acc[3][1], h01.y, w23.y);
        fma2(acc[3][2], h23.x, w23.y); fma2(acc[3][3], h23.y, w23.y);
    }

    float av[4][8];
    #pragma unroll
    for (int f = 0; f < 4; f++)
        #pragma unroll
        for (int p = 0; p < 4; p++) {
            float2 t = upk2(acc[f][p]);
            av[f][2 * p] = t.x;
            av[f][2 * p + 1] = t.y;
        }

    float4 cas = *reinterpret_cast<const float4*>(&asrc[f0]);
    float4 cad = *reinterpret_cast<const float4*>(&adst[f0]);
    float vs[8], vd[8];
    #pragma unroll
    for (int j = 0; j < 8; j++) {
        int n = n0 + nn0 + j;
        if (n < N) {
            __half2 p0 = __floats2half2_rn(av[0][j], av[1][j]);
            __half2 p1 = __floats2half2_rn(av[2][j], av[3][j]);
            __half2* gp = reinterpret_cast<__half2*>(&g_gh[(size_t)n * F1 + f0]);
            gp[0] = p0;
            gp[1] = p1;
        }
        vs[j] = av[0][j] * cas.x + av[1][j] * cas.y + av[2][j] * cas.z + av[3][j] * cas.w;
        vd[j] = av[0][j] * cad.x + av[1][j] * cad.y + av[2][j] * cad.z + av[3][j] * cad.w;
    }
    #pragma unroll
    for (int j = 0; j < 8; j++) {
        #pragma unroll
        for (int m = 4; m <= 16; m <<= 1) {
            vs[j] += __shfl_xor_sync(0xffffffffu, vs[j], m);
            vd[j] += __shfl_xor_sync(0xffffffffu, vd[j], m);
        }
    }
    if ((tid & 28) == 0) {
        int h = tid >> 5;
        #pragma unroll
        for (int j = 0; j < 8; j++) {
            int n = n0 + nn0 + j;
            if (n < N) {
                g_als[n * HEADS + h] = vs[j];
                g_ald[n * HEADS + h] = vd[j];
            }
        }
    }
}

// ---------------- CSR build --------------------------------------------------
__global__ void k_hist(const int* __restrict__ dst, int M) {
    int e = blockIdx.x * blockDim.x + threadIdx.x;
    if (e < M) atomicAdd(&g_cnt[__ldcs(&dst[e])], 1);
}
__global__ void k_scan1(int N) {
    __shared__ int sh[1024];
    int tid = threadIdx.x;
    int i = blockIdx.x * 1024 + tid;
    int v = (i < N) ? g_cnt[i] : 0;
    sh[tid] = v;
    __syncthreads();
    for (int o = 1; o < 1024; o <<= 1) {
        int t = (tid >= o) ? sh[tid - o] : 0;
        __syncthreads();
        sh[tid] += t;
        __syncthreads();
    }
    if (i < N) g_off[i] = sh[tid] - v;
    if (tid == 1023) g_bsum[blockIdx.x] = sh[1023];
}
__global__ void k_scan3(int nb, int N, int M) {
    __shared__ int sh[128];
    int tid = threadIdx.x;
    if (tid < 128) {
        int v = (tid < nb) ? g_bsum[tid] : 0;
        sh[tid] = v;
    }
    __syncthreads();
    if (tid < 128) {
        for (int o = 1; o < 128; o <<= 1) {
            int t = (tid >= o) ? sh[tid - o] : 0;
            __syncthreads();
            sh[tid] += t;
            __syncthreads();
        }
    } else {
        for (int o = 1; o < 128; o <<= 1) { __syncthreads(); __syncthreads(); }
    }
    int i = blockIdx.x * blockDim.x + tid;
    if (i < N) {
        int blk = i >> 10;
        int ex = (blk == 0) ? 0 : sh[blk - 1];
        int v = g_off[i] + ex;
        g_off[i] = v;
        g_cur[i] = v;
    }
    if (i == 0) g_off[N] = M;
}
__global__ void k_scatter(const int* __restrict__ src, const int* __restrict__ dst, int M) {
    int e = blockIdx.x * blockDim.x + threadIdx.x;
    if (e < M) {
        int d = __ldcs(&dst[e]);
        int p = atomicAdd(&g_cur[d], 1);
        g_srcs[p] = __ldcs(&src[e]);
    }
}

// ---------------- GAT aggregation (4 warps/node; fp16 gathers) --------------
__global__ void k_agg(const float* __restrict__ bias, int concat, int N) {
    int n = blockIdx.x;
    if (n >= N) return;
    int h = threadIdx.x >> 5;
    int lane = threadIdx.x & 31;
    int beg = g_off[n], end = g_off[n + 1];

    float ad = g_ald[n * HEADS + h];
    float ws = __expf(lrelu02(g_als[n * HEADS + h] + ad));

    const __half* gg = g_gh + (h << 5) + lane;
    float acc = ws * __half2float(gg[(size_t)n * F1]);
    float psum = 0.f;
    for (int base = beg; base < end; base += 32) {
        int j = base + lane;
        float w = 0.f;
        int s = 0;
        if (j < end) {
            s = g_srcs[j];
            w = __expf(lrelu02(g_als[s * HEADS + h] + ad));
            psum += w;
        }
        int lim = min(32, end - base);
        int kk = 0;
        for (; kk + 4 <= lim; kk += 4) {
            float w0 = __shfl_sync(0xffffffffu, w, kk);
            float w1 = __shfl_sync(0xffffffffu, w, kk + 1);
            float w2 = __shfl_sync(0xffffffffu, w, kk + 2);
            float w3 = __shfl_sync(0xffffffffu, w, kk + 3);
            int s0 = __shfl_sync(0xffffffffu, s, kk);
            int s1 = __shfl_sync(0xffffffffu, s, kk + 1);
            int s2 = __shfl_sync(0xffffffffu, s, kk + 2);
            int s3 = __shfl_sync(0xffffffffu, s, kk + 3);
            float v0 = __half2float(gg[(size_t)s0 * F1]);
            float v1 = __half2float(gg[(size_t)s1 * F1]);
            float v2 = __half2float(gg[(size_t)s2 * F1]);
            float v3 = __half2float(gg[(size_t)s3 * F1]);
            acc += w0 * v0;
            acc += w1 * v1;
            acc += w2 * v2;
            acc += w3 * v3;
        }
        for (; kk < lim; kk++) {
            float wk = __shfl_sync(0xffffffffu, w, kk);
            int sk = __shfl_sync(0xffffffffu, s, kk);
            acc += wk * __half2float(gg[(size_t)sk * F1]);
        }
    }
    #pragma unroll
    for (int o = 16; o; o >>= 1) psum += __shfl_xor_sync(0xffffffffu, psum, o);
    float v = acc / (psum + ws);

    if (concat) {
        v += bias[(h << 5) + lane];
        __stcs(&g_h1[n * F1 + (h << 5) + lane], eluf(v));
    } else {
        __shared__ float sm[F1];
        sm[(h << 5) + lane] = v;
        __syncthreads();
        if (h == 0) {
            float t = (sm[lane] + sm[32 + lane] + sm[64 + lane] + sm[96 + lane]) * 0.25f
                      + bias[lane];
            g_h2[n * HID + lane] = eluf(t);
        }
    }
}

// ---------------- decoder precompute: pa/pb (fp16 out) ----------------------
__global__ __launch_bounds__(256) void k_pab(const float* __restrict__ dw1, int N) {
    __shared__ float sdw[64 * 65];
    __shared__ float sh2[16 * 32];
    int tid = threadIdx.x;
    for (int i = tid; i < 64 * 64; i += 256) {
        int o = i >> 6, k = i & 63;
        sdw[o * 65 + k] = dw1[o * DEC_IN + k];
    }
    int n0 = blockIdx.x * 16;
    for (int i = tid; i < 16 * 32; i += 256) {
        int nl = i >> 5, k = i & 31;
        int n = n0 + nl;
        sh2[i] = (n < N) ? g_h2[n * HID + k] : 0.f;
    }
    __syncthreads();
    int o = tid & 63, ng = tid >> 6;
    float pa[4] = {0.f, 0.f, 0.f, 0.f}, pb[4] = {0.f, 0.f, 0.f, 0.f};
    #pragma unroll
    for (int k = 0; k < 32; k++) {
        float wa = sdw[o * 65 + k];
        float wb = sdw[o * 65 + 32 + k];
        #pragma unroll
        for (int j = 0; j < 4; j++) {
            float hv = sh2[(ng * 4 + j) * 32 + k];
            pa[j] += wa * hv;
            pb[j] += wb * hv;
        }
    }
    #pragma unroll
    for (int j = 0; j < 4; j++) {
        int n = n0 + ng * 4 + j;
        if (n < N) {
            g_pah[n * 64 + o] = __float2half_rn(pa[j]);
            g_pbh[n * 64 + o] = __float2half_rn(pb[j]);
        }
    }
}

// ---------------- decoder: 64-edge tiles; GEMM2 4e x 4o (R11 shape) ---------
#define TB 64
#define ZS (TB + 4)
__global__ __launch_bounds__(256) void k_dec(
    const int* __restrict__ ei, const float* __restrict__ eattr,
    const float* __restrict__ dw1, const float* __restrict__ db1,
    const float* __restrict__ db2, const float* __restrict__ dw3,
    const float* __restrict__ db3, float* __restrict__ out, int M) {
    __shared__ __align__(16) ull sw2p[DEC_H1 * DEC_H2];
    __shared__ float sw3[DEC_H2 * DEC_OUT];
    __shared__ float sb2[DEC_H2];
    __shared__ float sb3[DEC_OUT];
    __shared__ float sw1c[EDGE_DIM * 64];
    __shared__ float sdb1[64];
    __shared__ int ssrc[TB], sdst[TB];
    __shared__ float eat[TB * EDGE_DIM];
    __shared__ __align__(16) float z1t[DEC_H1 * ZS];
    __shared__ __align__(16) float z2t[DEC_H2 * ZS];
    int tid = threadIdx.x;

    for (int i = tid; i < DEC_H1 * DEC_H2; i += 256) {
        float w = g_w2t[i];
        sw2p[i] = pk2(w, w);
    }
    if (tid < 128) sw3[tid] = dw3[tid];
    if (tid < 64)  sdb1[tid] = db1[tid];
    if (tid < 32)  sb2[tid] = db2[tid];
    if (tid < 4)   sb3[tid] = db3[tid];
    for (int i = tid; i < EDGE_DIM * 64; i += 256) {
        int k = i >> 6, o = i & 63;
        sw1c[i] = dw1[o * DEC_IN + 64 + k];
    }

    const int* srcp = ei;
    const int* dstp = ei + M;
    int ntiles = (M + TB - 1) / TB;
    int eg = tid & 15, og = tid >> 4;
    int e0 = eg * 4, o0 = og * 4;

    for (int tile = blockIdx.x; tile < ntiles; tile += gridDim.x) {
        int eb = tile * TB;
        int nE = min(TB, M - eb);
        __syncthreads();
        if (tid < TB) {
            ssrc[tid] = (tid < nE) ? __ldcs(&srcp[eb + tid]) : 0;
            sdst[tid] = (tid < nE) ? __ldcs(&dstp[eb + tid]) : 0;
        }
        for (int i = tid; i < TB * EDGE_DIM; i += 256) {
            int gi = eb * EDGE_DIM + i;
            eat[i] = (gi < M * EDGE_DIM) ? __ldcs(&eattr[gi]) : 0.f;
        }
        __syncthreads();

        for (int i = tid; i < TB * 64; i += 256) {
            int e = i >> 6, o = i & 63;
            float v = __half2float(g_pah[(size_t)ssrc[e] * 64 + o])
                    + __half2float(g_pbh[(size_t)sdst[e] * 64 + o])
                    + sdb1[o];
            #pragma unroll
            for (int k = 0; k < EDGE_DIM; k++) v += sw1c[k * 64 + o] * eat[e * EDGE_DIM + k];
            z1t[o * ZS + e] = fmaxf(v, 0.f);
        }
        __syncthreads();

        if (tid < 128) {
            ull acc[4][2];
            #pragma unroll
            for (int a = 0; a < 4; a++) { acc[a][0] = 0ull; acc[a][1] = 0ull; }
            #pragma unroll 8
            for (int k = 0; k < DEC_H1; k++) {
                ulonglong2 zp = *reinterpret_cast<const ulonglong2*>(&z1t[k * ZS + e0]);
                ulonglong2 w01 = *reinterpret_cast<const ulonglong2*>(&sw2p[k * DEC_H2 + o0]);
                ulonglong2 w23 = *reinterpret_cast<const ulonglong2*>(&sw2p[k * DEC_H2 + o0 + 2]);
                fma2(acc[0][0], zp.x, w01.x); fma2(acc[0][1], zp.y, w01.x);
                fma2(acc[1][0], zp.x, w01.y); fma2(acc[1][1], zp.y, w01.y);
                fma2(acc[2][0], zp.x, w23.x); fma2(acc[2][1], zp.y, w23.x);
                fma2(acc[3][0], zp.x, w23.y); fma2(acc[3][1], zp.y, w23.y);
            }
            #pragma unroll
            for (int o = 0; o < 4; o++) {
                float b = sb2[o0 + o];
                float2 t0 = upk2(acc[o][0]);
                float2 t1 = upk2(acc[o][1]);
                float4 ov = make_float4(fmaxf(t0.x + b, 0.f), fmaxf(t0.y + b, 0.f),
                                        fmaxf(t1.x + b, 0.f), fmaxf(t1.y + b, 0.f));
                *reinterpret_cast<float4*>(&z2t[(o0 + o) * ZS + e0]) = ov;
            }
        }
        __syncthreads();

        {
            int e = tid & 63, o = tid >> 6;
            float acc = sb3[o];
            #pragma unroll
            for (int k = 0; k < DEC_H2; k++) acc += z2t[k * ZS + e] * sw3[o * DEC_H2 + k];
            if (e < nE) __stcs(&out[(eb + e) * DEC_OUT + o], acc);
        }
    }
}

// ---------------- launch -----------------------------------------------------
extern "C" void kernel_launch(void* const* d_in, const int* in_sizes, int n_in,
                              void* d_out, int out_size) {
    const float* x     = (const float*)d_in[0];
    const int*   ei    = (const int*)d_in[1];
    const float* eattr = (const float*)d_in[2];
    const float* u     = (const float*)d_in[3];
    const float* W1    = (const float*)d_in[4];
    const float* as1   = (const float*)d_in[5];
    const float* ad1   = (const float*)d_in[6];
    const float* b1    = (const float*)d_in[7];
    const float* W2    = (const float*)d_in[8];
    const float* as2   = (const float*)d_in[9];
    const float* ad2   = (const float*)d_in[10];
    const float* b2    = (const float*)d_in[11];
    const float* dw1   = (const float*)d_in[12];
    const float* db1   = (const float*)d_in[13];
    const float* dw2   = (const float*)d_in[14];
    const float* db2   = (const float*)d_in[15];
    const float* dw3   = (const float*)d_in[16];
    const float* db3   = (const float*)d_in[17];
    float* out = (float*)d_out;

    int N = in_sizes[0] / IN_NODE;
    int M = in_sizes[1] / 2;
    if (N > NMAX || M > EMAX || N <= 0 || M <= 0) return;

    const int* srcp = ei;
    const int* dstp = ei + M;
    int nb = (N + 1023) / 1024;

    k_prep_all<<<65 + (N + 255) / 256, 256>>>(u, W1, dw2, W2, N);
    k_hist<<<(M + 255) / 256, 256>>>(dstp, M);
    k_scan1<<<nb, 1024>>>(N);
    k_scan3<<<(N + 255) / 256, 256>>>(nb, N, M);
    k_scatter<<<(M + 255) / 256, 256>>>(srcp, dstp, M);

    k_gemm1<<<(N + G1N - 1) / G1N, 128>>>(x, as1, ad1, N);
    k_agg<<<N, 128>>>(b1, 1, N);

    k_gemm2<<<(N + G2N - 1) / G2N, 128>>>(as2, ad2, N);
    k_agg<<<N, 128>>>(b2, 0, N);

    k_pab<<<(N + 15) / 16, 256>>>(dw1, N);
    k_dec<<<1184, 256>>>(ei, eattr, dw1, db1, db2, dw3, db3, out, M);
}

// round 14
// speedup vs baseline: 1.5581x; 1.2895x over previous
#include <cuda_runtime.h>
#include <cuda_fp16.h>
#include <math.h>

#define NMAX 100000
#define EMAX 1600000
#define HEADS 4
#define HID 32
#define F1 128
#define IN_NODE 12
#define IN_GLB 11
#define IN1 23
#define EDGE_DIM 5
#define DEC_IN 69
#define DEC_H1 64
#define DEC_H2 32
#define DEC_OUT 4

typedef unsigned long long ull;
typedef unsigned int u32;

__device__ __align__(16) __half g_gh[NMAX * F1];
__device__ float g_h1[NMAX * F1];
__device__ float g_h2[NMAX * HID];
__device__ __align__(16) __half g_pah[NMAX * DEC_H1];
__device__ __align__(16) __half g_pbh[NMAX * DEC_H1];
__device__ __align__(16) float g_als[NMAX * HEADS];
__device__ __align__(16) float g_ald[NMAX * HEADS];
__device__ int   g_cnt[NMAX];
__device__ int   g_off[NMAX + 1];
__device__ int   g_cur[NMAX];
__device__ int   g_srcs[EMAX];
__device__ int   g_bsum[128];
__device__ float g_t1[F1];
__device__ float g_w1tt[IN_NODE * F1];
__device__ float g_w2t[DEC_H1 * DEC_H2];
__device__ __align__(16) ull g_w2p[F1 * F1];

__device__ __forceinline__ float lrelu02(float x) { return x > 0.f ? x : 0.2f * x; }
__device__ __forceinline__ float eluf(float x)    { return x > 0.f ? x : expm1f(x); }

__device__ __forceinline__ ull pk2(float lo, float hi) {
    ull r;
    asm("mov.b64 %0, {%1, %2};" : "=l"(r) : "f"(lo), "f"(hi));
    return r;
}
__device__ __forceinline__ void fma2(ull& d, ull a, ull b) {
    asm("fma.rn.f32x2 %0, %1, %2, %0;" : "+l"(d) : "l"(a), "l"(b));
}
__device__ __forceinline__ float2 upk2(ull v) {
    float2 f;
    asm("mov.b64 {%0, %1}, %2;" : "=f"(f.x), "=f"(f.y) : "l"(v));
    return f;
}

// ---- tensor-core helpers (warp-level HMMA) ----------------------------------
__device__ __forceinline__ void ldsm_x4(u32& r0, u32& r1, u32& r2, u32& r3, u32 addr) {
    asm volatile("ldmatrix.sync.aligned.m8n8.x4.shared.b16 {%0,%1,%2,%3}, [%4];"
                 : "=r"(r0), "=r"(r1), "=r"(r2), "=r"(r3) : "r"(addr));
}
__device__ __forceinline__ void ldsm_x2_trans(u32& r0, u32& r1, u32 addr) {
    asm volatile("ldmatrix.sync.aligned.m8n8.x2.trans.shared.b16 {%0,%1}, [%2];"
                 : "=r"(r0), "=r"(r1) : "r"(addr));
}
__device__ __forceinline__ void mma16816(float* c, const u32* a, const u32* b) {
    asm volatile("mma.sync.aligned.m16n8k16.row.col.f32.f16.f16.f32 "
                 "{%0,%1,%2,%3}, {%4,%5,%6,%7}, {%8,%9}, {%0,%1,%2,%3};"
                 : "+f"(c[0]), "+f"(c[1]), "+f"(c[2]), "+f"(c[3])
                 : "r"(a[0]), "r"(a[1]), "r"(a[2]), "r"(a[3]), "r"(b[0]), "r"(b[1]));
}

// ---------------- merged prep: zero cnt + t1/w1tt/w2t + w2p -----------------
__global__ void k_prep_all(const float* __restrict__ u, const float* __restrict__ W1,
                           const float* __restrict__ dw2, const float* __restrict__ W2,
                           int N) {
    int b = blockIdx.x;
    int tid = threadIdx.x;
    if (b < 64) {
        int i = b * 256 + tid;
        int k = i >> 7, f = i & 127;
        float w = W2[f * F1 + k];
        g_w2p[i] = pk2(w, w);
    } else if (b == 64) {
        if (tid < F1) {
            float s = 0.f;
            #pragma unroll
            for (int k = 0; k < IN_GLB; k++) s += u[k] * W1[tid * IN1 + IN_NODE + k];
            g_t1[tid] = s;
        }
        for (int i = tid; i < IN_NODE * F1; i += 256) {
            int k = i >> 7, f = i & 127;
            g_w1tt[i] = W1[f * IN1 + k];
        }
        for (int i = tid; i < DEC_H1 * DEC_H2; i += 256) {
            int k = i >> 5, o = i & 31;
            g_w2t[i] = dw2[o * DEC_H1 + k];
        }
    } else {
        int i = (b - 65) * 256 + tid;
        if (i < N) g_cnt[i] = 0;
    }
}

// ---------------- layer-1 node transform (8 nodes/block) --------------------
#define G1N 8
__global__ __launch_bounds__(128) void k_gemm1(const float* __restrict__ x,
                        const float* __restrict__ asrc, const float* __restrict__ adst,
                        int N) {
    int n0 = blockIdx.x * G1N;
    int f = threadIdx.x;
    __shared__ float xs[G1N][IN_NODE];
    if (f < G1N * IN_NODE) {
        int i = f / IN_NODE, k = f - i * IN_NODE;
        int n = n0 + i;
        xs[i][k] = (n < N) ? __ldcs(&x[n * IN_NODE + k]) : 0.f;
    }
    __syncthreads();
    float acc[G1N];
    float t = g_t1[f];
    #pragma unroll
    for (int i = 0; i < G1N; i++) acc[i] = t;
    #pragma unroll
    for (int k = 0; k < IN_NODE; k++) {
        float w = g_w1tt[k * F1 + f];
        #pragma unroll
        for (int i = 0; i < G1N; i++) acc[i] += xs[i][k] * w;
    }
    int h = f >> 5;
    float cas = asrc[f], cad = adst[f];
    #pragma unroll
    for (int i = 0; i < G1N; i++) {
        int n = n0 + i;
        if (n >= N) break;
        g_gh[n * F1 + f] = __float2half_rn(acc[i]);
        float vs = acc[i] * cas, vd = acc[i] * cad;
        #pragma unroll
        for (int o = 16; o; o >>= 1) {
            vs += __shfl_xor_sync(0xffffffffu, vs, o);
            vd += __shfl_xor_sync(0xffffffffu, vd, o);
        }
        if ((f & 31) == 0) {
            g_als[n * HEADS + h] = vs;
            g_ald[n * HEADS + h] = vd;
        }
    }
}

// ---------------- layer-2 node transform: 32 nodes/block, 4f x 8n tiles -----
#define G2N 32
#define HSTS 36
__global__ __launch_bounds__(128) void k_gemm2(const float* __restrict__ asrc,
                                               const float* __restrict__ adst,
                                               int N) {
    __shared__ __align__(16) float hst[F1 * HSTS];
    int tid = threadIdx.x;
    int n0 = blockIdx.x * G2N;

    for (int i = tid; i < G2N * (F1 / 4); i += 128) {
        int n = i >> 5, f4 = i & 31;
        float4 hv = make_float4(0.f, 0.f, 0.f, 0.f);
        if (n0 + n < N)
            hv = __ldcs(reinterpret_cast<const float4*>(&g_h1[(size_t)(n0 + n) * F1 + 4 * f4]));
        hst[(4 * f4 + 0) * HSTS + n] = hv.x;
        hst[(4 * f4 + 1) * HSTS + n] = hv.y;
        hst[(4 * f4 + 2) * HSTS + n] = hv.z;
        hst[(4 * f4 + 3) * HSTS + n] = hv.w;
    }
    __syncthreads();

    int fq = tid >> 2, nq = tid & 3;
    int f0 = fq * 4, nn0 = nq * 8;

    ull acc[4][4];
    #pragma unroll
    for (int a = 0; a < 4; a++)
        #pragma unroll
        for (int b = 0; b < 4; b++) acc[a][b] = 0ull;

    #pragma unroll 4
    for (int k = 0; k < F1; k++) {
        ulonglong2 h01 = *reinterpret_cast<const ulonglong2*>(&hst[k * HSTS + nn0]);
        ulonglong2 h23 = *reinterpret_cast<const ulonglong2*>(&hst[k * HSTS + nn0 + 4]);
        const ulonglong2* wp = reinterpret_cast<const ulonglong2*>(&g_w2p[(size_t)k * F1 + f0]);
        ulonglong2 w01 = wp[0];
        ulonglong2 w23 = wp[1];
        fma2(acc[0][0], h01.x, w01.x); fma2(acc[0][1], h01.y, w01.x);
        fma2(acc[0][2], h23.x, w01.x); fma2(acc[0][3], h23.y, w01.x);
        fma2(acc[1][0], h01.x, w01.y); fma2(acc[1][1], h01.y, w01.y);
        fma2(acc[1][2], h23.x, w01.y); fma2(acc[1][3], h23.y, w01.y);
        fma2(acc[2][0], h01.x, w23.x); fma2(acc[2][1], h01.y, w23.x);
        fma2(acc[2][2], h23.x, w23.x); fma2(acc[2][3], h23.y, w23.x);
        fma2(acc[3][0], h01.x, w23.y); fma2(acc[3][1], h01.y, w23.y);
        fma2(acc[3][2], h23.x, w23.y); fma2(acc[3][3], h23.y, w23.y);
    }

    float av[4][8];
    #pragma unroll
    for (int f = 0; f < 4; f++)
        #pragma unroll
        for (int p = 0; p < 4; p++) {
            float2 t = upk2(acc[f][p]);
            av[f][2 * p] = t.x;
            av[f][2 * p + 1] = t.y;
        }

    float4 cas = *reinterpret_cast<const float4*>(&asrc[f0]);
    float4 cad = *reinterpret_cast<const float4*>(&adst[f0]);
    float vs[8], vd[8];
    #pragma unroll
    for (int j = 0; j < 8; j++) {
        int n = n0 + nn0 + j;
        if (n < N) {
            __half2 p0 = __floats2half2_rn(av[0][j], av[1][j]);
            __half2 p1 = __floats2half2_rn(av[2][j], av[3][j]);
            __half2* gp = reinterpret_cast<__half2*>(&g_gh[(size_t)n * F1 + f0]);
            gp[0] = p0;
            gp[1] = p1;
        }
        vs[j] = av[0][j] * cas.x + av[1][j] * cas.y + av[2][j] * cas.z + av[3][j] * cas.w;
        vd[j] = av[0][j] * cad.x + av[1][j] * cad.y + av[2][j] * cad.z + av[3][j] * cad.w;
    }
    #pragma unroll
    for (int j = 0; j < 8; j++) {
        #pragma unroll
        for (int m = 4; m <= 16; m <<= 1) {
            vs[j] += __shfl_xor_sync(0xffffffffu, vs[j], m);
            vd[j] += __shfl_xor_sync(0xffffffffu, vd[j], m);
        }
    }
    if ((tid & 28) == 0) {
        int h = tid >> 5;
        #pragma unroll
        for (int j = 0; j < 8; j++) {
            int n = n0 + nn0 + j;
            if (n < N) {
                g_als[n * HEADS + h] = vs[j];
                g_ald[n * HEADS + h] = vd[j];
            }
        }
    }
}

// ---------------- CSR build --------------------------------------------------
__global__ void k_hist(const int* __restrict__ dst, int M) {
    int e = blockIdx.x * blockDim.x + threadIdx.x;
    if (e < M) atomicAdd(&g_cnt[__ldcs(&dst[e])], 1);
}
__global__ void k_scan1(int N) {
    __shared__ int sh[1024];
    int tid = threadIdx.x;
    int i = blockIdx.x * 1024 + tid;
    int v = (i < N) ? g_cnt[i] : 0;
    sh[tid] = v;
    __syncthreads();
    for (int o = 1; o < 1024; o <<= 1) {
        int t = (tid >= o) ? sh[tid - o] : 0;
        __syncthreads();
        sh[tid] += t;
        __syncthreads();
    }
    if (i < N) g_off[i] = sh[tid] - v;
    if (tid == 1023) g_bsum[blockIdx.x] = sh[1023];
}
__global__ void k_scan3(int nb, int N, int M) {
    __shared__ int sh[128];
    int tid = threadIdx.x;
    if (tid < 128) {
        int v = (tid < nb) ? g_bsum[tid] : 0;
        sh[tid] = v;
    }
    __syncthreads();
    if (tid < 128) {
        for (int o = 1; o < 128; o <<= 1) {
            int t = (tid >= o) ? sh[tid - o] : 0;
            __syncthreads();
            sh[tid] += t;
            __syncthreads();
        }
    } else {
        for (int o = 1; o < 128; o <<= 1) { __syncthreads(); __syncthreads(); }
    }
    int i = blockIdx.x * blockDim.x + tid;
    if (i < N) {
        int blk = i >> 10;
        int ex = (blk == 0) ? 0 : sh[blk - 1];
        int v = g_off[i] + ex;
        g_off[i] = v;
        g_cur[i] = v;
    }
    if (i == 0) g_off[N] = M;
}
__global__ void k_scatter(const int* __restrict__ src, const int* __restrict__ dst, int M) {
    int e = blockIdx.x * blockDim.x + threadIdx.x;
    if (e < M) {
        int d = __ldcs(&dst[e]);
        int p = atomicAdd(&g_cur[d], 1);
        g_srcs[p] = __ldcs(&src[e]);
    }
}

// ---------------- GAT aggregation (4 warps/node; fp16 gathers) --------------
__global__ void k_agg(const float* __restrict__ bias, int concat, int N) {
    int n = blockIdx.x;
    if (n >= N) return;
    int h = threadIdx.x >> 5;
    int lane = threadIdx.x & 31;
    int beg = g_off[n], end = g_off[n + 1];

    float ad = g_ald[n * HEADS + h];
    float ws = __expf(lrelu02(g_als[n * HEADS + h] + ad));

    const __half* gg = g_gh + (h << 5) + lane;
    float acc = ws * __half2float(gg[(size_t)n * F1]);
    float psum = 0.f;
    for (int base = beg; base < end; base += 32) {
        int j = base + lane;
        float w = 0.f;
        int s = 0;
        if (j < end) {
            s = g_srcs[j];
            w = __expf(lrelu02(g_als[s * HEADS + h] + ad));
            psum += w;
        }
        int lim = min(32, end - base);
        int kk = 0;
        for (; kk + 4 <= lim; kk += 4) {
            float w0 = __shfl_sync(0xffffffffu, w, kk);
            float w1 = __shfl_sync(0xffffffffu, w, kk + 1);
            float w2 = __shfl_sync(0xffffffffu, w, kk + 2);
            float w3 = __shfl_sync(0xffffffffu, w, kk + 3);
            int s0 = __shfl_sync(0xffffffffu, s, kk);
            int s1 = __shfl_sync(0xffffffffu, s, kk + 1);
            int s2 = __shfl_sync(0xffffffffu, s, kk + 2);
            int s3 = __shfl_sync(0xffffffffu, s, kk + 3);
            float v0 = __half2float(gg[(size_t)s0 * F1]);
            float v1 = __half2float(gg[(size_t)s1 * F1]);
            float v2 = __half2float(gg[(size_t)s2 * F1]);
            float v3 = __half2float(gg[(size_t)s3 * F1]);
            acc += w0 * v0;
            acc += w1 * v1;
            acc += w2 * v2;
            acc += w3 * v3;
        }
        for (; kk < lim; kk++) {
            float wk = __shfl_sync(0xffffffffu, w, kk);
            int sk = __shfl_sync(0xffffffffu, s, kk);
            acc += wk * __half2float(gg[(size_t)sk * F1]);
        }
    }
    #pragma unroll
    for (int o = 16; o; o >>= 1) psum += __shfl_xor_sync(0xffffffffu, psum, o);
    float v = acc / (psum + ws);

    if (concat) {
        v += bias[(h << 5) + lane];
        __stcs(&g_h1[n * F1 + (h << 5) + lane], eluf(v));
    } else {
        __shared__ float sm[F1];
        sm[(h << 5) + lane] = v;
        __syncthreads();
        if (h == 0) {
            float t = (sm[lane] + sm[32 + lane] + sm[64 + lane] + sm[96 + lane]) * 0.25f
                      + bias[lane];
            g_h2[n * HID + lane] = eluf(t);
        }
    }
}

// ---------------- decoder precompute: pa/pb (fp16 out) ----------------------
__global__ __launch_bounds__(256) void k_pab(const float* __restrict__ dw1, int N) {
    __shared__ float sdw[64 * 65];
    __shared__ float sh2[16 * 32];
    int tid = threadIdx.x;
    for (int i = tid; i < 64 * 64; i += 256) {
        int o = i >> 6, k = i & 63;
        sdw[o * 65 + k] = dw1[o * DEC_IN + k];
    }
    int n0 = blockIdx.x * 16;
    for (int i = tid; i < 16 * 32; i += 256) {
        int nl = i >> 5, k = i & 31;
        int n = n0 + nl;
        sh2[i] = (n < N) ? g_h2[n * HID + k] : 0.f;
    }
    __syncthreads();
    int o = tid & 63, ng = tid >> 6;
    float pa[4] = {0.f, 0.f, 0.f, 0.f}, pb[4] = {0.f, 0.f, 0.f, 0.f};
    #pragma unroll
    for (int k = 0; k < 32; k++) {
        float wa = sdw[o * 65 + k];
        float wb = sdw[o * 65 + 32 + k];
        #pragma unroll
        for (int j = 0; j < 4; j++) {
            float hv = sh2[(ng * 4 + j) * 32 + k];
            pa[j] += wa * hv;
            pb[j] += wb * hv;
        }
    }
    #pragma unroll
    for (int j = 0; j < 4; j++) {
        int n = n0 + ng * 4 + j;
        if (n < N) {
            g_pah[n * 64 + o] = __float2half_rn(pa[j]);
            g_pbh[n * 64 + o] = __float2half_rn(pb[j]);
        }
    }
}

// ---------------- decoder: 64-edge tiles; GEMM2 via HMMA tensor cores -------
#define TB 64
#define ZS (TB + 4)
#define Z1S 72   // z1h row stride in halves (144 B, 16B-aligned)
__global__ __launch_bounds__(256) void k_dec(
    const int* __restrict__ ei, const float* __restrict__ eattr,
    const float* __restrict__ dw1, const float* __restrict__ db1,
    const float* __restrict__ db2, const float* __restrict__ dw3,
    const float* __restrict__ db3, float* __restrict__ out, int M) {
    __shared__ __align__(16) __half w2h[DEC_H1 * DEC_H2];   // [k][o], 4 KB
    __shared__ __align__(16) __half z1h[TB * Z1S];          // [e][k], 9216 B
    __shared__ __align__(16) float z2t[DEC_H2 * ZS];        // [o][e]
    __shared__ float sw3[DEC_H2 * DEC_OUT];
    __shared__ float sb2[DEC_H2];
    __shared__ float sb3[DEC_OUT];
    __shared__ float sw1c[EDGE_DIM * 64];
    __shared__ float sdb1[64];
    __shared__ int ssrc[TB], sdst[TB];
    __shared__ float eat[TB * EDGE_DIM];
    int tid = threadIdx.x;
    int lane = tid & 31;
    int wid = tid >> 5;

    for (int i = tid; i < DEC_H1 * DEC_H2; i += 256)
        w2h[i] = __float2half_rn(g_w2t[i]);
    if (tid < 128) sw3[tid] = dw3[tid];
    if (tid < 64)  sdb1[tid] = db1[tid];
    if (tid < 32)  sb2[tid] = db2[tid];
    if (tid < 4)   sb3[tid] = db3[tid];
    for (int i = tid; i < EDGE_DIM * 64; i += 256) {
        int k = i >> 6, o = i & 63;
        sw1c[i] = dw1[o * DEC_IN + 64 + k];
    }
    __syncthreads();

    // warp roles: eb = (wid>>1)*16 (edge rows), oh = (wid&1)*16 (output cols)
    int eb = (wid >> 1) * 16;
    int oh = (wid & 1) * 16;

    // preload B fragments: bf[kt][nt2][2]
    u32 bf[4][2][2];
    {
        u32 wbase = (u32)__cvta_generic_to_shared(w2h);
        #pragma unroll
        for (int kt = 0; kt < 4; kt++)
            #pragma unroll
            for (int nt2 = 0; nt2 < 2; nt2++) {
                u32 addr = wbase + (((kt * 16 + (lane & 15)) * DEC_H2) + oh + nt2 * 8) * 2;
                ldsm_x2_trans(bf[kt][nt2][0], bf[kt][nt2][1], addr);
            }
    }
    u32 z1base = (u32)__cvta_generic_to_shared(z1h);

    const int* srcp = ei;
    const int* dstp = ei + M;
    int ntiles = (M + TB - 1) / TB;

    for (int tile = blockIdx.x; tile < ntiles; tile += gridDim.x) {
        int ebb = tile * TB;
        int nE = min(TB, M - ebb);
        __syncthreads();
        if (tid < TB) {
            ssrc[tid] = (tid < nE) ? __ldcs(&srcp[ebb + tid]) : 0;
            sdst[tid] = (tid < nE) ? __ldcs(&dstp[ebb + tid]) : 0;
        }
        for (int i = tid; i < TB * EDGE_DIM; i += 256) {
            int gi = ebb * EDGE_DIM + i;
            eat[i] = (gi < M * EDGE_DIM) ? __ldcs(&eattr[gi]) : 0.f;
        }
        __syncthreads();

        // phase A: z1[e][o0,o0+1] pairs (half2 loads of pa/pb)
        for (int i = tid; i < TB * 32; i += 256) {
            int e = i >> 5, oq = i & 31;
            int o0 = oq * 2;
            float2 pa = __half22float2(
                *reinterpret_cast<const __half2*>(&g_pah[(size_t)ssrc[e] * 64 + o0]));
            float2 pb = __half22float2(
                *reinterpret_cast<const __half2*>(&g_pbh[(size_t)sdst[e] * 64 + o0]));
            float v0 = pa.x + pb.x + sdb1[o0];
            float v1 = pa.y + pb.y + sdb1[o0 + 1];
            #pragma unroll
            for (int k = 0; k < EDGE_DIM; k++) {
                float ea = eat[e * EDGE_DIM + k];
                v0 += sw1c[k * 64 + o0] * ea;
                v1 += sw1c[k * 64 + o0 + 1] * ea;
            }
            *reinterpret_cast<__half2*>(&z1h[e * Z1S + o0]) =
                __floats2half2_rn(fmaxf(v0, 0.f), fmaxf(v1, 0.f));
        }
        __syncthreads();

        // phase B: GEMM2 via mma.m16n8k16 (all 8 warps)
        {
            float acc[2][4];
            #pragma unroll
            for (int n = 0; n < 2; n++)
                #pragma unroll
                for (int c = 0; c < 4; c++) acc[n][c] = 0.f;
            #pragma unroll
            for (int kt = 0; kt < 4; kt++) {
                u32 a[4];
                u32 addr = z1base + ((eb + (lane & 15)) * Z1S + kt * 16 + (lane >> 4) * 8) * 2;
                ldsm_x4(a[0], a[1], a[2], a[3], addr);
                mma16816(acc[0], a, bf[kt][0]);
                mma16816(acc[1], a, bf[kt][1]);
            }
            int g = lane >> 2, t4 = lane & 3;
            #pragma unroll
            for (int nt2 = 0; nt2 < 2; nt2++) {
                int ob = oh + nt2 * 8 + t4 * 2;
                float b0 = sb2[ob], b1 = sb2[ob + 1];
                z2t[ob * ZS + eb + g]           = fmaxf(acc[nt2][0] + b0, 0.f);
                z2t[(ob + 1) * ZS + eb + g]     = fmaxf(acc[nt2][1] + b1, 0.f);
                z2t[ob * ZS + eb + g + 8]       = fmaxf(acc[nt2][2] + b0, 0.f);
                z2t[(ob + 1) * ZS + eb + g + 8] = fmaxf(acc[nt2][3] + b1, 0.f);
            }
        }
        __syncthreads();

        // phase C: GEMM3 (64e x 4o, K=32)
        {
            int e = tid & 63, o = tid >> 6;
            float acc = sb3[o];
            #pragma unroll
            for (int k = 0; k < DEC_H2; k++) acc += z2t[k * ZS + e] * sw3[o * DEC_H2 + k];
            if (e < nE) __stcs(&out[(ebb + e) * DEC_OUT + o], acc);
        }
    }
}

// ---------------- launch -----------------------------------------------------
extern "C" void kernel_launch(void* const* d_in, const int* in_sizes, int n_in,
                              void* d_out, int out_size) {
    const float* x     = (const float*)d_in[0];
    const int*   ei    = (const int*)d_in[1];
    const float* eattr = (const float*)d_in[2];
    const float* u     = (const float*)d_in[3];
    const float* W1    = (const float*)d_in[4];
    const float* as1   = (const float*)d_in[5];
    const float* ad1   = (const float*)d_in[6];
    const float* b1    = (const float*)d_in[7];
    const float* W2    = (const float*)d_in[8];
    const float* as2   = (const float*)d_in[9];
    const float* ad2   = (const float*)d_in[10];
    const float* b2    = (const float*)d_in[11];
    const float* dw1   = (const float*)d_in[12];
    const float* db1   = (const float*)d_in[13];
    const float* dw2   = (const float*)d_in[14];
    const float* db2   = (const float*)d_in[15];
    const float* dw3   = (const float*)d_in[16];
    const float* db3   = (const float*)d_in[17];
    float* out = (float*)d_out;

    int N = in_sizes[0] / IN_NODE;
    int M = in_sizes[1] / 2;
    if (N > NMAX || M > EMAX || N <= 0 || M <= 0) return;

    const int* srcp = ei;
    const int* dstp = ei + M;
    int nb = (N + 1023) / 1024;

    k_prep_all<<<65 + (N + 255) / 256, 256>>>(u, W1, dw2, W2, N);
    k_hist<<<(M + 255) / 256, 256>>>(dstp, M);
    k_scan1<<<nb, 1024>>>(N);
    k_scan3<<<(N + 255) / 256, 256>>>(nb, N, M);
    k_scatter<<<(M + 255) / 256, 256>>>(srcp, dstp, M);

    k_gemm1<<<(N + G1N - 1) / G1N, 128>>>(x, as1, ad1, N);
    k_agg<<<N, 128>>>(b1, 1, N);

    k_gemm2<<<(N + G2N - 1) / G2N, 128>>>(as2, ad2, N);
    k_agg<<<N, 128>>>(b2, 0, N);

    k_pab<<<(N + 15) / 16, 256>>>(dw1, N);
    k_dec<<<1184, 256>>>(ei, eattr, dw1, db1, db2, dw3, db3, out, M);
}

// round 16
// speedup vs baseline: 1.5956x; 1.0241x over previous
#include <cuda_runtime.h>
#include <cuda_fp16.h>
#include <math.h>

#define NMAX 100000
#define EMAX 1600000
#define HEADS 4
#define HID 32
#define F1 128
#define IN_NODE 12
#define IN_GLB 11
#define IN1 23
#define EDGE_DIM 5
#define DEC_IN 69
#define DEC_H1 64
#define DEC_H2 32
#define DEC_OUT 4

typedef unsigned long long ull;
typedef unsigned int u32;

__device__ __align__(16) __half g_gh[NMAX * F1];
__device__ __align__(16) __half g_h1h[NMAX * F1];
__device__ float g_h2[NMAX * HID];
__device__ __align__(16) __half g_pah[NMAX * DEC_H1];
__device__ __align__(16) __half g_pbh[NMAX * DEC_H1];
__device__ __align__(16) float g_als[NMAX * HEADS];
__device__ __align__(16) float g_ald[NMAX * HEADS];
__device__ int   g_cnt[NMAX];
__device__ int   g_off[NMAX + 1];
__device__ int   g_cur[NMAX];
__device__ int   g_srcs[EMAX];
__device__ int   g_bsum[128];
__device__ float g_t1[F1];
__device__ float g_w1tt[IN_NODE * F1];
__device__ float g_w2t[DEC_H1 * DEC_H2];
__device__ __align__(16) __half g_w2ht[F1 * F1];   // W2^T fp16: [k][f]

__device__ __forceinline__ float lrelu02(float x) { return x > 0.f ? x : 0.2f * x; }
__device__ __forceinline__ float eluf(float x)    { return x > 0.f ? x : expm1f(x); }

// ---- tensor-core helpers ----------------------------------------------------
__device__ __forceinline__ void ldsm_x4(u32& r0, u32& r1, u32& r2, u32& r3, u32 addr) {
    asm volatile("ldmatrix.sync.aligned.m8n8.x4.shared.b16 {%0,%1,%2,%3}, [%4];"
                 : "=r"(r0), "=r"(r1), "=r"(r2), "=r"(r3) : "r"(addr));
}
__device__ __forceinline__ void ldsm_x2_trans(u32& r0, u32& r1, u32 addr) {
    asm volatile("ldmatrix.sync.aligned.m8n8.x2.trans.shared.b16 {%0,%1}, [%2];"
                 : "=r"(r0), "=r"(r1) : "r"(addr));
}
__device__ __forceinline__ void mma16816(float* c, const u32* a, const u32* b) {
    asm volatile("mma.sync.aligned.m16n8k16.row.col.f32.f16.f16.f32 "
                 "{%0,%1,%2,%3}, {%4,%5,%6,%7}, {%8,%9}, {%0,%1,%2,%3};"
                 : "+f"(c[0]), "+f"(c[1]), "+f"(c[2]), "+f"(c[3])
                 : "r"(a[0]), "r"(a[1]), "r"(a[2]), "r"(a[3]), "r"(b[0]), "r"(b[1]));
}

// ---------------- merged prep: zero cnt + t1/w1tt/w2t + w2ht ----------------
__global__ void k_prep_all(const float* __restrict__ u, const float* __restrict__ W1,
                           const float* __restrict__ dw2, const float* __restrict__ W2,
                           int N) {
    int b = blockIdx.x;
    int tid = threadIdx.x;
    if (b < 64) {
        int i = b * 256 + tid;       // 16384 entries: [k][f]
        int k = i >> 7, f = i & 127;
        g_w2ht[i] = __float2half_rn(W2[f * F1 + k]);
    } else if (b == 64) {
        if (tid < F1) {
            float s = 0.f;
            #pragma unroll
            for (int k = 0; k < IN_GLB; k++) s += u[k] * W1[tid * IN1 + IN_NODE + k];
            g_t1[tid] = s;
        }
        for (int i = tid; i < IN_NODE * F1; i += 256) {
            int k = i >> 7, f = i & 127;
            g_w1tt[i] = W1[f * IN1 + k];
        }
        for (int i = tid; i < DEC_H1 * DEC_H2; i += 256) {
            int k = i >> 5, o = i & 31;
            g_w2t[i] = dw2[o * DEC_H1 + k];
        }
    } else {
        int i = (b - 65) * 256 + tid;
        if (i < N) g_cnt[i] = 0;
    }
}

// ---------------- layer-1 node transform (8 nodes/block) --------------------
#define G1N 8
__global__ __launch_bounds__(128) void k_gemm1(const float* __restrict__ x,
                        const float* __restrict__ asrc, const float* __restrict__ adst,
                        int N) {
    int n0 = blockIdx.x * G1N;
    int f = threadIdx.x;
    __shared__ float xs[G1N][IN_NODE];
    if (f < G1N * IN_NODE) {
        int i = f / IN_NODE, k = f - i * IN_NODE;
        int n = n0 + i;
        xs[i][k] = (n < N) ? __ldcs(&x[n * IN_NODE + k]) : 0.f;
    }
    __syncthreads();
    float acc[G1N];
    float t = g_t1[f];
    #pragma unroll
    for (int i = 0; i < G1N; i++) acc[i] = t;
    #pragma unroll
    for (int k = 0; k < IN_NODE; k++) {
        float w = g_w1tt[k * F1 + f];
        #pragma unroll
        for (int i = 0; i < G1N; i++) acc[i] += xs[i][k] * w;
    }
    int h = f >> 5;
    float cas = asrc[f], cad = adst[f];
    #pragma unroll
    for (int i = 0; i < G1N; i++) {
        int n = n0 + i;
        if (n >= N) break;
        g_gh[n * F1 + f] = __float2half_rn(acc[i]);
        float vs = acc[i] * cas, vd = acc[i] * cad;
        #pragma unroll
        for (int o = 16; o; o >>= 1) {
            vs += __shfl_xor_sync(0xffffffffu, vs, o);
            vd += __shfl_xor_sync(0xffffffffu, vd, o);
        }
        if ((f & 31) == 0) {
            g_als[n * HEADS + h] = vs;
            g_ald[n * HEADS + h] = vd;
        }
    }
}

// ---------------- layer-2 node transform via HMMA (8 warps: full coverage) --
#define G2N 32
#define H1S 136   // h1 tile stride in halves (272 B, 16B-aligned)
__global__ __launch_bounds__(256) void k_gemm2(int N) {
    __shared__ __align__(16) __half h1s[G2N * H1S];
    __shared__ __align__(16) __half w2s[F1 * F1];   // [k][f]
    int tid = threadIdx.x;
    int lane = tid & 31;
    int wid = tid >> 5;
    int n0 = blockIdx.x * G2N;

    // stage W2^T fp16 (coalesced uint4): 2048 uint4 over 256 threads
    for (int i = tid * 8; i < F1 * F1; i += 256 * 8)
        *reinterpret_cast<uint4*>(&w2s[i]) = *reinterpret_cast<const uint4*>(&g_w2ht[i]);
    // stage h1 tile (fp16, coalesced): 512 uint4
    for (int i = tid; i < G2N * (F1 / 8); i += 256) {
        int n = i >> 4, kq = i & 15;
        uint4 v = make_uint4(0u, 0u, 0u, 0u);
        if (n0 + n < N)
            v = *reinterpret_cast<const uint4*>(&g_h1h[(size_t)(n0 + n) * F1 + kq * 8]);
        *reinterpret_cast<uint4*>(&h1s[n * H1S + kq * 8]) = v;
    }
    __syncthreads();

    int m0 = (wid & 1) * 16;        // node rows: 2 tiles
    int f0 = (wid >> 1) * 32;       // output features: 4 tiles of 32 -> full 128
    float c[4][4];
    #pragma unroll
    for (int a = 0; a < 4; a++)
        #pragma unroll
        for (int b = 0; b < 4; b++) c[a][b] = 0.f;

    u32 h1base = (u32)__cvta_generic_to_shared(h1s);
    u32 w2base = (u32)__cvta_generic_to_shared(w2s);
    #pragma unroll
    for (int kt = 0; kt < 8; kt++) {
        u32 a[4];
        ldsm_x4(a[0], a[1], a[2], a[3],
                h1base + ((m0 + (lane & 15)) * H1S + kt * 16 + (lane >> 4) * 8) * 2);
        #pragma unroll
        for (int nb = 0; nb < 4; nb++) {
            u32 b[2];
            ldsm_x2_trans(b[0], b[1],
                          w2base + ((kt * 16 + (lane & 15)) * F1 + f0 + nb * 8) * 2);
            mma16816(c[nb], a, b);
        }
    }

    int g = lane >> 2, t4 = lane & 3;
    #pragma unroll
    for (int nb = 0; nb < 4; nb++) {
        int col = f0 + nb * 8 + t4 * 2;
        int na = n0 + m0 + g;
        int nbn = na + 8;
        if (na < N)
            *reinterpret_cast<__half2*>(&g_gh[(size_t)na * F1 + col]) =
                __floats2half2_rn(c[nb][0], c[nb][1]);
        if (nbn < N)
            *reinterpret_cast<__half2*>(&g_gh[(size_t)nbn * F1 + col]) =
                __floats2half2_rn(c[nb][2], c[nb][3]);
    }
}

// ---------------- layer-2 attention logits from g_gh ------------------------
__global__ __launch_bounds__(512) void k_logits(const float* __restrict__ asrc,
                                                const float* __restrict__ adst, int N) {
    int tid = threadIdx.x;
    int n = blockIdx.x * 4 + (tid >> 7);
    int f = tid & 127;
    if (n >= N) return;
    float gv = __half2float(g_gh[(size_t)n * F1 + f]);
    float vs = gv * asrc[f], vd = gv * adst[f];
    #pragma unroll
    for (int o = 16; o; o >>= 1) {
        vs += __shfl_xor_sync(0xffffffffu, vs, o);
        vd += __shfl_xor_sync(0xffffffffu, vd, o);
    }
    if ((f & 31) == 0) {
        int h = f >> 5;
        g_als[n * HEADS + h] = vs;
        g_ald[n * HEADS + h] = vd;
    }
}

// ---------------- CSR build --------------------------------------------------
__global__ void k_hist(const int* __restrict__ dst, int M) {
    int e = blockIdx.x * blockDim.x + threadIdx.x;
    if (e < M) atomicAdd(&g_cnt[__ldcs(&dst[e])], 1);
}
__global__ void k_scan1(int N) {
    __shared__ int sh[1024];
    int tid = threadIdx.x;
    int i = blockIdx.x * 1024 + tid;
    int v = (i < N) ? g_cnt[i] : 0;
    sh[tid] = v;
    __syncthreads();
    for (int o = 1; o < 1024; o <<= 1) {
        int t = (tid >= o) ? sh[tid - o] : 0;
        __syncthreads();
        sh[tid] += t;
        __syncthreads();
    }
    if (i < N) g_off[i] = sh[tid] - v;
    if (tid == 1023) g_bsum[blockIdx.x] = sh[1023];
}
__global__ void k_scan3(int nb, int N, int M) {
    __shared__ int sh[128];
    int tid = threadIdx.x;
    if (tid < 128) {
        int v = (tid < nb) ? g_bsum[tid] : 0;
        sh[tid] = v;
    }
    __syncthreads();
    if (tid < 128) {
        for (int o = 1; o < 128; o <<= 1) {
            int t = (tid >= o) ? sh[tid - o] : 0;
            __syncthreads();
            sh[tid] += t;
            __syncthreads();
        }
    } else {
        for (int o = 1; o < 128; o <<= 1) { __syncthreads(); __syncthreads(); }
    }
    int i = blockIdx.x * blockDim.x + tid;
    if (i < N) {
        int blk = i >> 10;
        int ex = (blk == 0) ? 0 : sh[blk - 1];
        int v = g_off[i] + ex;
        g_off[i] = v;
        g_cur[i] = v;
    }
    if (i == 0) g_off[N] = M;
}
__global__ void k_scatter(const int* __restrict__ src, const int* __restrict__ dst, int M) {
    int e = blockIdx.x * blockDim.x + threadIdx.x;
    if (e < M) {
        int d = __ldcs(&dst[e]);
        int p = atomicAdd(&g_cur[d], 1);
        g_srcs[p] = __ldcs(&src[e]);
    }
}

// ---------------- GAT aggregation (4 warps/node; fp16 gathers) --------------
__global__ void k_agg(const float* __restrict__ bias, int concat, int N) {
    int n = blockIdx.x;
    if (n >= N) return;
    int h = threadIdx.x >> 5;
    int lane = threadIdx.x & 31;
    int beg = g_off[n], end = g_off[n + 1];

    float ad = g_ald[n * HEADS + h];
    float ws = __expf(lrelu02(g_als[n * HEADS + h] + ad));

    const __half* gg = g_gh + (h << 5) + lane;
    float acc = ws * __half2float(gg[(size_t)n * F1]);
    float psum = 0.f;
    for (int base = beg; base < end; base += 32) {
        int j = base + lane;
        float w = 0.f;
        int s = 0;
        if (j < end) {
            s = g_srcs[j];
            w = __expf(lrelu02(g_als[s * HEADS + h] + ad));
            psum += w;
        }
        int lim = min(32, end - base);
        int kk = 0;
        for (; kk + 4 <= lim; kk += 4) {
            float w0 = __shfl_sync(0xffffffffu, w, kk);
            float w1 = __shfl_sync(0xffffffffu, w, kk + 1);
            float w2 = __shfl_sync(0xffffffffu, w, kk + 2);
            float w3 = __shfl_sync(0xffffffffu, w, kk + 3);
            int s0 = __shfl_sync(0xffffffffu, s, kk);
            int s1 = __shfl_sync(0xffffffffu, s, kk + 1);
            int s2 = __shfl_sync(0xffffffffu, s, kk + 2);
            int s3 = __shfl_sync(0xffffffffu, s, kk + 3);
            float v0 = __half2float(gg[(size_t)s0 * F1]);
            float v1 = __half2float(gg[(size_t)s1 * F1]);
            float v2 = __half2float(gg[(size_t)s2 * F1]);
            float v3 = __half2float(gg[(size_t)s3 * F1]);
            acc += w0 * v0;
            acc += w1 * v1;
            acc += w2 * v2;
            acc += w3 * v3;
        }
        for (; kk < lim; kk++) {
            float wk = __shfl_sync(0xffffffffu, w, kk);
            int sk = __shfl_sync(0xffffffffu, s, kk);
            acc += wk * __half2float(gg[(size_t)sk * F1]);
        }
    }
    #pragma unroll
    for (int o = 16; o; o >>= 1) psum += __shfl_xor_sync(0xffffffffu, psum, o);
    float v = acc / (psum + ws);

    if (concat) {
        v += bias[(h << 5) + lane];
        g_h1h[n * F1 + (h << 5) + lane] = __float2half_rn(eluf(v));
    } else {
        __shared__ float sm[F1];
        sm[(h << 5) + lane] = v;
        __syncthreads();
        if (h == 0) {
            float t = (sm[lane] + sm[32 + lane] + sm[64 + lane] + sm[96 + lane]) * 0.25f
                      + bias[lane];
            g_h2[n * HID + lane] = eluf(t);
        }
    }
}

// ---------------- decoder precompute: pa/pb (fp16 out) ----------------------
__global__ __launch_bounds__(256) void k_pab(const float* __restrict__ dw1, int N) {
    __shared__ float sdw[64 * 65];
    __shared__ float sh2[16 * 32];
    int tid = threadIdx.x;
    for (int i = tid; i < 64 * 64; i += 256) {
        int o = i >> 6, k = i & 63;
        sdw[o * 65 + k] = dw1[o * DEC_IN + k];
    }
    int n0 = blockIdx.x * 16;
    for (int i = tid; i < 16 * 32; i += 256) {
        int nl = i >> 5, k = i & 31;
        int n = n0 + nl;
        sh2[i] = (n < N) ? g_h2[n * HID + k] : 0.f;
    }
    __syncthreads();
    int o = tid & 63, ng = tid >> 6;
    float pa[4] = {0.f, 0.f, 0.f, 0.f}, pb[4] = {0.f, 0.f, 0.f, 0.f};
    #pragma unroll
    for (int k = 0; k < 32; k++) {
        float wa = sdw[o * 65 + k];
        float wb = sdw[o * 65 + 32 + k];
        #pragma unroll
        for (int j = 0; j < 4; j++) {
            float hv = sh2[(ng * 4 + j) * 32 + k];
            pa[j] += wa * hv;
            pb[j] += wb * hv;
        }
    }
    #pragma unroll
    for (int j = 0; j < 4; j++) {
        int n = n0 + ng * 4 + j;
        if (n < N) {
            g_pah[n * 64 + o] = __float2half_rn(pa[j]);
            g_pbh[n * 64 + o] = __float2half_rn(pb[j]);
        }
    }
}

// ---------------- decoder: 64-edge tiles; GEMM2 via HMMA (R14) --------------
#define TB 64
#define ZS (TB + 4)
#define Z1S 72
__global__ __launch_bounds__(256) void k_dec(
    const int* __restrict__ ei, const float* __restrict__ eattr,
    const float* __restrict__ dw1, const float* __restrict__ db1,
    const float* __restrict__ db2, const float* __restrict__ dw3,
    const float* __restrict__ db3, float* __restrict__ out, int M) {
    __shared__ __align__(16) __half w2h[DEC_H1 * DEC_H2];
    __shared__ __align__(16) __half z1h[TB * Z1S];
    __shared__ __align__(16) float z2t[DEC_H2 * ZS];
    __shared__ float sw3[DEC_H2 * DEC_OUT];
    __shared__ float sb2[DEC_H2];
    __shared__ float sb3[DEC_OUT];
    __shared__ float sw1c[EDGE_DIM * 64];
    __shared__ float sdb1[64];
    __shared__ int ssrc[TB], sdst[TB];
    __shared__ float eat[TB * EDGE_DIM];
    int tid = threadIdx.x;
    int lane = tid & 31;
    int wid = tid >> 5;

    for (int i = tid; i < DEC_H1 * DEC_H2; i += 256)
        w2h[i] = __float2half_rn(g_w2t[i]);
    if (tid < 128) sw3[tid] = dw3[tid];
    if (tid < 64)  sdb1[tid] = db1[tid];
    if (tid < 32)  sb2[tid] = db2[tid];
    if (tid < 4)   sb3[tid] = db3[tid];
    for (int i = tid; i < EDGE_DIM * 64; i += 256) {
        int k = i >> 6, o = i & 63;
        sw1c[i] = dw1[o * DEC_IN + 64 + k];
    }
    __syncthreads();

    int eb = (wid >> 1) * 16;
    int oh = (wid & 1) * 16;

    u32 bf[4][2][2];
    {
        u32 wbase = (u32)__cvta_generic_to_shared(w2h);
        #pragma unroll
        for (int kt = 0; kt < 4; kt++)
            #pragma unroll
            for (int nt2 = 0; nt2 < 2; nt2++) {
                u32 addr = wbase + (((kt * 16 + (lane & 15)) * DEC_H2) + oh + nt2 * 8) * 2;
                ldsm_x2_trans(bf[kt][nt2][0], bf[kt][nt2][1], addr);
            }
    }
    u32 z1base = (u32)__cvta_generic_to_shared(z1h);

    const int* srcp = ei;
    const int* dstp = ei + M;
    int ntiles = (M + TB - 1) / TB;

    for (int tile = blockIdx.x; tile < ntiles; tile += gridDim.x) {
        int ebb = tile * TB;
        int nE = min(TB, M - ebb);
        __syncthreads();
        if (tid < TB) {
            ssrc[tid] = (tid < nE) ? __ldcs(&srcp[ebb + tid]) : 0;
            sdst[tid] = (tid < nE) ? __ldcs(&dstp[ebb + tid]) : 0;
        }
        for (int i = tid; i < TB * EDGE_DIM; i += 256) {
            int gi = ebb * EDGE_DIM + i;
            eat[i] = (gi < M * EDGE_DIM) ? __ldcs(&eattr[gi]) : 0.f;
        }
        __syncthreads();

        for (int i = tid; i < TB * 32; i += 256) {
            int e = i >> 5, oq = i & 31;
            int o0 = oq * 2;
            float2 pa = __half22float2(
                *reinterpret_cast<const __half2*>(&g_pah[(size_t)ssrc[e] * 64 + o0]));
            float2 pb = __half22float2(
                *reinterpret_cast<const __half2*>(&g_pbh[(size_t)sdst[e] * 64 + o0]));
            float v0 = pa.x + pb.x + sdb1[o0];
            float v1 = pa.y + pb.y + sdb1[o0 + 1];
            #pragma unroll
            for (int k = 0; k < EDGE_DIM; k++) {
                float ea = eat[e * EDGE_DIM + k];
                v0 += sw1c[k * 64 + o0] * ea;
                v1 += sw1c[k * 64 + o0 + 1] * ea;
            }
            *reinterpret_cast<__half2*>(&z1h[e * Z1S + o0]) =
                __floats2half2_rn(fmaxf(v0, 0.f), fmaxf(v1, 0.f));
        }
        __syncthreads();

        {
            float acc[2][4];
            #pragma unroll
            for (int n = 0; n < 2; n++)
                #pragma unroll
                for (int c = 0; c < 4; c++) acc[n][c] = 0.f;
            #pragma unroll
            for (int kt = 0; kt < 4; kt++) {
                u32 a[4];
                u32 addr = z1base + ((eb + (lane & 15)) * Z1S + kt * 16 + (lane >> 4) * 8) * 2;
                ldsm_x4(a[0], a[1], a[2], a[3], addr);
                mma16816(acc[0], a, bf[kt][0]);
                mma16816(acc[1], a, bf[kt][1]);
            }
            int g = lane >> 2, t4 = lane & 3;
            #pragma unroll
            for (int nt2 = 0; nt2 < 2; nt2++) {
                int ob = oh + nt2 * 8 + t4 * 2;
                float b0 = sb2[ob], b1 = sb2[ob + 1];
                z2t[ob * ZS + eb + g]           = fmaxf(acc[nt2][0] + b0, 0.f);
                z2t[(ob + 1) * ZS + eb + g]     = fmaxf(acc[nt2][1] + b1, 0.f);
                z2t[ob * ZS + eb + g + 8]       = fmaxf(acc[nt2][2] + b0, 0.f);
                z2t[(ob + 1) * ZS + eb + g + 8] = fmaxf(acc[nt2][3] + b1, 0.f);
            }
        }
        __syncthreads();

        {
            int e = tid & 63, o = tid >> 6;
            float acc = sb3[o];
            #pragma unroll
            for (int k = 0; k < DEC_H2; k++) acc += z2t[k * ZS + e] * sw3[o * DEC_H2 + k];
            if (e < nE) __stcs(&out[(ebb + e) * DEC_OUT + o], acc);
        }
    }
}

// ---------------- launch -----------------------------------------------------
extern "C" void kernel_launch(void* const* d_in, const int* in_sizes, int n_in,
                              void* d_out, int out_size) {
    const float* x     = (const float*)d_in[0];
    const int*   ei    = (const int*)d_in[1];
    const float* eattr = (const float*)d_in[2];
    const float* u     = (const float*)d_in[3];
    const float* W1    = (const float*)d_in[4];
    const float* as1   = (const float*)d_in[5];
    const float* ad1   = (const float*)d_in[6];
    const float* b1    = (const float*)d_in[7];
    const float* W2    = (const float*)d_in[8];
    const float* as2   = (const float*)d_in[9];
    const float* ad2   = (const float*)d_in[10];
    const float* b2    = (const float*)d_in[11];
    const float* dw1   = (const float*)d_in[12];
    const float* db1   = (const float*)d_in[13];
    const float* dw2   = (const float*)d_in[14];
    const float* db2   = (const float*)d_in[15];
    const float* dw3   = (const float*)d_in[16];
    const float* db3   = (const float*)d_in[17];
    float* out = (float*)d_out;

    int N = in_sizes[0] / IN_NODE;
    int M = in_sizes[1] / 2;
    if (N > NMAX || M > EMAX || N <= 0 || M <= 0) return;

    const int* srcp = ei;
    const int* dstp = ei + M;
    int nb = (N + 1023) / 1024;

    k_prep_all<<<65 + (N + 255) / 256, 256>>>(u, W1, dw2, W2, N);
    k_hist<<<(M + 255) / 256, 256>>>(dstp, M);
    k_scan1<<<nb, 1024>>>(N);
    k_scan3<<<(N + 255) / 256, 256>>>(nb, N, M);
    k_scatter<<<(M + 255) / 256, 256>>>(srcp, dstp, M);

    k_gemm1<<<(N + G1N - 1) / G1N, 128>>>(x, as1, ad1, N);
    k_agg<<<N, 128>>>(b1, 1, N);

    k_gemm2<<<(N + G2N - 1) / G2N, 256>>>(N);
    k_logits<<<(N + 3) / 4, 512>>>(as2, ad2, N);
    k_agg<<<N, 128>>>(b2, 0, N);

    k_pab<<<(N + 15) / 16, 256>>>(dw1, N);
    k_dec<<<1184, 256>>>(ei, eattr, dw1, db1, db2, dw3, db3, out, M);
}

// round 17
// speedup vs baseline: 1.5973x; 1.0011x over previous
#include <cuda_runtime.h>
#include <cuda_fp16.h>
#include <math.h>

#define NMAX 100000
#define EMAX 1600000
#define HEADS 4
#define HID 32
#define F1 128
#define IN_NODE 12
#define IN_GLB 11
#define IN1 23
#define EDGE_DIM 5
#define DEC_IN 69
#define DEC_H1 64
#define DEC_H2 32
#define DEC_OUT 4

typedef unsigned long long ull;
typedef unsigned int u32;

__device__ __align__(16) __half g_gh[NMAX * F1];
__device__ __align__(16) __half g_h1h[NMAX * F1];
__device__ float g_h2[NMAX * HID];
__device__ __align__(16) __half g_pah[NMAX * DEC_H1];
__device__ __align__(16) __half g_pbh[NMAX * DEC_H1];
__device__ __align__(16) float g_als[NMAX * HEADS];
__device__ __align__(16) float g_ald[NMAX * HEADS];
__device__ int   g_cnt[NMAX];
__device__ int   g_off[NMAX + 1];
__device__ int   g_cur[NMAX];
__device__ int   g_srcs[EMAX];
__device__ int   g_bsum[128];
__device__ float g_t1[F1];
__device__ float g_w1tt[IN_NODE * F1];
__device__ float g_w2t[DEC_H1 * DEC_H2];
__device__ __align__(16) __half g_w2ht[F1 * F1];   // W2^T fp16: [k][f]

__device__ __forceinline__ float lrelu02(float x) { return x > 0.f ? x : 0.2f * x; }
__device__ __forceinline__ float eluf(float x)    { return x > 0.f ? x : expm1f(x); }

// ---- tensor-core helpers ----------------------------------------------------
__device__ __forceinline__ void ldsm_x4(u32& r0, u32& r1, u32& r2, u32& r3, u32 addr) {
    asm volatile("ldmatrix.sync.aligned.m8n8.x4.shared.b16 {%0,%1,%2,%3}, [%4];"
                 : "=r"(r0), "=r"(r1), "=r"(r2), "=r"(r3) : "r"(addr));
}
__device__ __forceinline__ void ldsm_x2_trans(u32& r0, u32& r1, u32 addr) {
    asm volatile("ldmatrix.sync.aligned.m8n8.x2.trans.shared.b16 {%0,%1}, [%2];"
                 : "=r"(r0), "=r"(r1) : "r"(addr));
}
__device__ __forceinline__ void mma16816(float* c, const u32* a, const u32* b) {
    asm volatile("mma.sync.aligned.m16n8k16.row.col.f32.f16.f16.f32 "
                 "{%0,%1,%2,%3}, {%4,%5,%6,%7}, {%8,%9}, {%0,%1,%2,%3};"
                 : "+f"(c[0]), "+f"(c[1]), "+f"(c[2]), "+f"(c[3])
                 : "r"(a[0]), "r"(a[1]), "r"(a[2]), "r"(a[3]), "r"(b[0]), "r"(b[1]));
}

// ---------------- merged prep: zero cnt + t1/w1tt/w2t + w2ht ----------------
__global__ void k_prep_all(const float* __restrict__ u, const float* __restrict__ W1,
                           const float* __restrict__ dw2, const float* __restrict__ W2,
                           int N) {
    int b = blockIdx.x;
    int tid = threadIdx.x;
    if (b < 64) {
        int i = b * 256 + tid;
        int k = i >> 7, f = i & 127;
        g_w2ht[i] = __float2half_rn(W2[f * F1 + k]);
    } else if (b == 64) {
        if (tid < F1) {
            float s = 0.f;
            #pragma unroll
            for (int k = 0; k < IN_GLB; k++) s += u[k] * W1[tid * IN1 + IN_NODE + k];
            g_t1[tid] = s;
        }
        for (int i = tid; i < IN_NODE * F1; i += 256) {
            int k = i >> 7, f = i & 127;
            g_w1tt[i] = W1[f * IN1 + k];
        }
        for (int i = tid; i < DEC_H1 * DEC_H2; i += 256) {
            int k = i >> 5, o = i & 31;
            g_w2t[i] = dw2[o * DEC_H1 + k];
        }
    } else {
        int i = (b - 65) * 256 + tid;
        if (i < N) g_cnt[i] = 0;
    }
}

// ---------------- layer-1 node transform (8 nodes/block) --------------------
#define G1N 8
__global__ __launch_bounds__(128) void k_gemm1(const float* __restrict__ x,
                        const float* __restrict__ asrc, const float* __restrict__ adst,
                        int N) {
    int n0 = blockIdx.x * G1N;
    int f = threadIdx.x;
    __shared__ float xs[G1N][IN_NODE];
    if (f < G1N * IN_NODE) {
        int i = f / IN_NODE, k = f - i * IN_NODE;
        int n = n0 + i;
        xs[i][k] = (n < N) ? __ldcs(&x[n * IN_NODE + k]) : 0.f;
    }
    __syncthreads();
    float acc[G1N];
    float t = g_t1[f];
    #pragma unroll
    for (int i = 0; i < G1N; i++) acc[i] = t;
    #pragma unroll
    for (int k = 0; k < IN_NODE; k++) {
        float w = g_w1tt[k * F1 + f];
        #pragma unroll
        for (int i = 0; i < G1N; i++) acc[i] += xs[i][k] * w;
    }
    int h = f >> 5;
    float cas = asrc[f], cad = adst[f];
    #pragma unroll
    for (int i = 0; i < G1N; i++) {
        int n = n0 + i;
        if (n >= N) break;
        g_gh[n * F1 + f] = __float2half_rn(acc[i]);
        float vs = acc[i] * cas, vd = acc[i] * cad;
        #pragma unroll
        for (int o = 16; o; o >>= 1) {
            vs += __shfl_xor_sync(0xffffffffu, vs, o);
            vd += __shfl_xor_sync(0xffffffffu, vd, o);
        }
        if ((f & 31) == 0) {
            g_als[n * HEADS + h] = vs;
            g_ald[n * HEADS + h] = vd;
        }
    }
}

// ---------------- layer-2 node transform via HMMA (64 nodes/block) ----------
#define G2N 64
#define H1S 136
__global__ __launch_bounds__(256) void k_gemm2(int N) {
    __shared__ __align__(16) __half h1s[G2N * H1S];
    __shared__ __align__(16) __half w2s[F1 * F1];   // [k][f]
    int tid = threadIdx.x;
    int lane = tid & 31;
    int wid = tid >> 5;
    int n0 = blockIdx.x * G2N;

    for (int i = tid * 8; i < F1 * F1; i += 256 * 8)
        *reinterpret_cast<uint4*>(&w2s[i]) = *reinterpret_cast<const uint4*>(&g_w2ht[i]);
    for (int i = tid; i < G2N * (F1 / 8); i += 256) {
        int n = i >> 4, kq = i & 15;
        uint4 v = make_uint4(0u, 0u, 0u, 0u);
        if (n0 + n < N)
            v = *reinterpret_cast<const uint4*>(&g_h1h[(size_t)(n0 + n) * F1 + kq * 8]);
        *reinterpret_cast<uint4*>(&h1s[n * H1S + kq * 8]) = v;
    }
    __syncthreads();

    int m0 = (wid & 3) * 16;        // 4 node-tiles -> 64 nodes
    int fh = wid >> 2;              // 2 feature halves of 64
    float c[2][4][4];
    #pragma unroll
    for (int ft = 0; ft < 2; ft++)
        #pragma unroll
        for (int a = 0; a < 4; a++)
            #pragma unroll
            for (int b = 0; b < 4; b++) c[ft][a][b] = 0.f;

    u32 h1base = (u32)__cvta_generic_to_shared(h1s);
    u32 w2base = (u32)__cvta_generic_to_shared(w2s);
    #pragma unroll
    for (int kt = 0; kt < 8; kt++) {
        u32 a[4];
        ldsm_x4(a[0], a[1], a[2], a[3],
                h1base + ((m0 + (lane & 15)) * H1S + kt * 16 + (lane >> 4) * 8) * 2);
        #pragma unroll
        for (int ft = 0; ft < 2; ft++) {
            int f0 = fh * 64 + ft * 32;
            #pragma unroll
            for (int nb = 0; nb < 4; nb++) {
                u32 b[2];
                ldsm_x2_trans(b[0], b[1],
                              w2base + ((kt * 16 + (lane & 15)) * F1 + f0 + nb * 8) * 2);
                mma16816(c[ft][nb], a, b);
            }
        }
    }

    int g = lane >> 2, t4 = lane & 3;
    #pragma unroll
    for (int ft = 0; ft < 2; ft++)
        #pragma unroll
        for (int nb = 0; nb < 4; nb++) {
            int col = fh * 64 + ft * 32 + nb * 8 + t4 * 2;
            int na = n0 + m0 + g;
            int nbn = na + 8;
            if (na < N)
                *reinterpret_cast<__half2*>(&g_gh[(size_t)na * F1 + col]) =
                    __floats2half2_rn(c[ft][nb][0], c[ft][nb][1]);
            if (nbn < N)
                *reinterpret_cast<__half2*>(&g_gh[(size_t)nbn * F1 + col]) =
                    __floats2half2_rn(c[ft][nb][2], c[ft][nb][3]);
        }
}

// ---------------- layer-2 attention logits from g_gh ------------------------
__global__ __launch_bounds__(512) void k_logits(const float* __restrict__ asrc,
                                                const float* __restrict__ adst, int N) {
    int tid = threadIdx.x;
    int n = blockIdx.x * 4 + (tid >> 7);
    int f = tid & 127;
    if (n >= N) return;
    float gv = __half2float(g_gh[(size_t)n * F1 + f]);
    float vs = gv * asrc[f], vd = gv * adst[f];
    #pragma unroll
    for (int o = 16; o; o >>= 1) {
        vs += __shfl_xor_sync(0xffffffffu, vs, o);
        vd += __shfl_xor_sync(0xffffffffu, vd, o);
    }
    if ((f & 31) == 0) {
        int h = f >> 5;
        g_als[n * HEADS + h] = vs;
        g_ald[n * HEADS + h] = vd;
    }
}

// ---------------- CSR build --------------------------------------------------
__global__ void k_hist(const int* __restrict__ dst, int M) {
    int e = blockIdx.x * blockDim.x + threadIdx.x;
    if (e < M) atomicAdd(&g_cnt[__ldcs(&dst[e])], 1);
}
__global__ void k_scan1(int N) {
    __shared__ int sh[1024];
    int tid = threadIdx.x;
    int i = blockIdx.x * 1024 + tid;
    int v = (i < N) ? g_cnt[i] : 0;
    sh[tid] = v;
    __syncthreads();
    for (int o = 1; o < 1024; o <<= 1) {
        int t = (tid >= o) ? sh[tid - o] : 0;
        __syncthreads();
        sh[tid] += t;
        __syncthreads();
    }
    if (i < N) g_off[i] = sh[tid] - v;
    if (tid == 1023) g_bsum[blockIdx.x] = sh[1023];
}
__global__ void k_scan3(int nb, int N, int M) {
    __shared__ int sh[128];
    int tid = threadIdx.x;
    if (tid < 128) {
        int v = (tid < nb) ? g_bsum[tid] : 0;
        sh[tid] = v;
    }
    __syncthreads();
    if (tid < 128) {
        for (int o = 1; o < 128; o <<= 1) {
            int t = (tid >= o) ? sh[tid - o] : 0;
            __syncthreads();
            sh[tid] += t;
            __syncthreads();
        }
    } else {
        for (int o = 1; o < 128; o <<= 1) { __syncthreads(); __syncthreads(); }
    }
    int i = blockIdx.x * blockDim.x + tid;
    if (i < N) {
        int blk = i >> 10;
        int ex = (blk == 0) ? 0 : sh[blk - 1];
        int v = g_off[i] + ex;
        g_off[i] = v;
        g_cur[i] = v;
    }
    if (i == 0) g_off[N] = M;
}
__global__ void k_scatter(const int* __restrict__ src, const int* __restrict__ dst, int M) {
    int e = blockIdx.x * blockDim.x + threadIdx.x;
    if (e < M) {
        int d = __ldcs(&dst[e]);
        int p = atomicAdd(&g_cur[d], 1);
        g_srcs[p] = __ldcs(&src[e]);
    }
}

// ---------------- GAT aggregation (4 warps/node; fp16 gathers) --------------
__global__ void k_agg(const float* __restrict__ bias, int concat, int N) {
    int n = blockIdx.x;
    if (n >= N) return;
    int h = threadIdx.x >> 5;
    int lane = threadIdx.x & 31;
    int beg = g_off[n], end = g_off[n + 1];

    float ad = g_ald[n * HEADS + h];
    float ws = __expf(lrelu02(g_als[n * HEADS + h] + ad));

    const __half* gg = g_gh + (h << 5) + lane;
    float acc = ws * __half2float(gg[(size_t)n * F1]);
    float psum = 0.f;
    for (int base = beg; base < end; base += 32) {
        int j = base + lane;
        float w = 0.f;
        int s = 0;
        if (j < end) {
            s = g_srcs[j];
            w = __expf(lrelu02(g_als[s * HEADS + h] + ad));
            psum += w;
        }
        int lim = min(32, end - base);
        int kk = 0;
        for (; kk + 4 <= lim; kk += 4) {
            float w0 = __shfl_sync(0xffffffffu, w, kk);
            float w1 = __shfl_sync(0xffffffffu, w, kk + 1);
            float w2 = __shfl_sync(0xffffffffu, w, kk + 2);
            float w3 = __shfl_sync(0xffffffffu, w, kk + 3);
            int s0 = __shfl_sync(0xffffffffu, s, kk);
            int s1 = __shfl_sync(0xffffffffu, s, kk + 1);
            int s2 = __shfl_sync(0xffffffffu, s, kk + 2);
            int s3 = __shfl_sync(0xffffffffu, s, kk + 3);
            float v0 = __half2float(gg[(size_t)s0 * F1]);
            float v1 = __half2float(gg[(size_t)s1 * F1]);
            float v2 = __half2float(gg[(size_t)s2 * F1]);
            float v3 = __half2float(gg[(size_t)s3 * F1]);
            acc += w0 * v0;
            acc += w1 * v1;
            acc += w2 * v2;
            acc += w3 * v3;
        }
        for (; kk < lim; kk++) {
            float wk = __shfl_sync(0xffffffffu, w, kk);
            int sk = __shfl_sync(0xffffffffu, s, kk);
            acc += wk * __half2float(gg[(size_t)sk * F1]);
        }
    }
    #pragma unroll
    for (int o = 16; o; o >>= 1) psum += __shfl_xor_sync(0xffffffffu, psum, o);
    float v = acc / (psum + ws);

    if (concat) {
        v += bias[(h << 5) + lane];
        g_h1h[n * F1 + (h << 5) + lane] = __float2half_rn(eluf(v));
    } else {
        __shared__ float sm[F1];
        sm[(h << 5) + lane] = v;
        __syncthreads();
        if (h == 0) {
            float t = (sm[lane] + sm[32 + lane] + sm[64 + lane] + sm[96 + lane]) * 0.25f
                      + bias[lane];
            g_h2[n * HID + lane] = eluf(t);
        }
    }
}

// ---------------- decoder precompute: pa/pb (fp16 out) ----------------------
__global__ __launch_bounds__(256) void k_pab(const float* __restrict__ dw1, int N) {
    __shared__ float sdw[64 * 65];
    __shared__ float sh2[16 * 32];
    int tid = threadIdx.x;
    for (int i = tid; i < 64 * 64; i += 256) {
        int o = i >> 6, k = i & 63;
        sdw[o * 65 + k] = dw1[o * DEC_IN + k];
    }
    int n0 = blockIdx.x * 16;
    for (int i = tid; i < 16 * 32; i += 256) {
        int nl = i >> 5, k = i & 31;
        int n = n0 + nl;
        sh2[i] = (n < N) ? g_h2[n * HID + k] : 0.f;
    }
    __syncthreads();
    int o = tid & 63, ng = tid >> 6;
    float pa[4] = {0.f, 0.f, 0.f, 0.f}, pb[4] = {0.f, 0.f, 0.f, 0.f};
    #pragma unroll
    for (int k = 0; k < 32; k++) {
        float wa = sdw[o * 65 + k];
        float wb = sdw[o * 65 + 32 + k];
        #pragma unroll
        for (int j = 0; j < 4; j++) {
            float hv = sh2[(ng * 4 + j) * 32 + k];
            pa[j] += wa * hv;
            pb[j] += wb * hv;
        }
    }
    #pragma unroll
    for (int j = 0; j < 4; j++) {
        int n = n0 + ng * 4 + j;
        if (n < N) {
            g_pah[n * 64 + o] = __float2half_rn(pa[j]);
            g_pbh[n * 64 + o] = __float2half_rn(pb[j]);
        }
    }
}

// ---------------- decoder: HMMA GEMM2 + HMMA GEMM3 --------------------------
#define TB 64
#define Z1S 72
#define Z2S 40   // z2 fp16 [e][k] stride (80 B)
__global__ __launch_bounds__(256) void k_dec(
    const int* __restrict__ ei, const float* __restrict__ eattr,
    const float* __restrict__ dw1, const float* __restrict__ db1,
    const float* __restrict__ db2, const float* __restrict__ dw3,
    const float* __restrict__ db3, float* __restrict__ out, int M) {
    __shared__ __align__(16) __half w2h[DEC_H1 * DEC_H2];
    __shared__ __align__(16) __half z1h[TB * Z1S];
    __shared__ __align__(16) __half z2h[TB * Z2S];     // [e][k] fp16
    __shared__ __align__(16) __half sw3t[DEC_H2 * 8];  // dw3^T [k][o<=8]
    __shared__ float sb2[DEC_H2];
    __shared__ float sb3[DEC_OUT];
    __shared__ float sw1c[EDGE_DIM * 64];
    __shared__ float sdb1[64];
    __shared__ int ssrc[TB], sdst[TB];
    __shared__ float eat[TB * EDGE_DIM];
    int tid = threadIdx.x;
    int lane = tid & 31;
    int wid = tid >> 5;

    for (int i = tid; i < DEC_H1 * DEC_H2; i += 256)
        w2h[i] = __float2half_rn(g_w2t[i]);
    if (tid < DEC_H2 * 8) {
        int k = tid >> 3, o = tid & 7;
        sw3t[tid] = (o < DEC_OUT) ? __float2half_rn(dw3[o * DEC_H2 + k]) : __half(0.f);
    }
    if (tid < 64)  sdb1[tid] = db1[tid];
    if (tid < 32)  sb2[tid] = db2[tid];
    if (tid < 4)   sb3[tid] = db3[tid];
    for (int i = tid; i < EDGE_DIM * 64; i += 256) {
        int k = i >> 6, o = i & 63;
        sw1c[i] = dw1[o * DEC_IN + 64 + k];
    }
    __syncthreads();

    int eb = (wid >> 1) * 16;
    int oh = (wid & 1) * 16;

    // B fragments for GEMM2 (w2) and GEMM3 (dw3^T)
    u32 bf[4][2][2];
    u32 bf3[2][2];
    {
        u32 wbase = (u32)__cvta_generic_to_shared(w2h);
        #pragma unroll
        for (int kt = 0; kt < 4; kt++)
            #pragma unroll
            for (int nt2 = 0; nt2 < 2; nt2++) {
                u32 addr = wbase + (((kt * 16 + (lane & 15)) * DEC_H2) + oh + nt2 * 8) * 2;
                ldsm_x2_trans(bf[kt][nt2][0], bf[kt][nt2][1], addr);
            }
        u32 w3base = (u32)__cvta_generic_to_shared(sw3t);
        #pragma unroll
        for (int kt = 0; kt < 2; kt++)
            ldsm_x2_trans(bf3[kt][0], bf3[kt][1],
                          w3base + ((kt * 16 + (lane & 15)) * 8) * 2);
    }
    u32 z1base = (u32)__cvta_generic_to_shared(z1h);
    u32 z2base = (u32)__cvta_generic_to_shared(z2h);

    const int* srcp = ei;
    const int* dstp = ei + M;
    int ntiles = (M + TB - 1) / TB;

    for (int tile = blockIdx.x; tile < ntiles; tile += gridDim.x) {
        int ebb = tile * TB;
        int nE = min(TB, M - ebb);
        __syncthreads();
        if (tid < TB) {
            ssrc[tid] = (tid < nE) ? __ldcs(&srcp[ebb + tid]) : 0;
            sdst[tid] = (tid < nE) ? __ldcs(&dstp[ebb + tid]) : 0;
        }
        for (int i = tid; i < TB * EDGE_DIM; i += 256) {
            int gi = ebb * EDGE_DIM + i;
            eat[i] = (gi < M * EDGE_DIM) ? __ldcs(&eattr[gi]) : 0.f;
        }
        __syncthreads();

        // phase A: z1 fp16 [e][k]
        for (int i = tid; i < TB * 32; i += 256) {
            int e = i >> 5, oq = i & 31;
            int o0 = oq * 2;
            float2 pa = __half22float2(
                *reinterpret_cast<const __half2*>(&g_pah[(size_t)ssrc[e] * 64 + o0]));
            float2 pb = __half22float2(
                *reinterpret_cast<const __half2*>(&g_pbh[(size_t)sdst[e] * 64 + o0]));
            float v0 = pa.x + pb.x + sdb1[o0];
            float v1 = pa.y + pb.y + sdb1[o0 + 1];
            #pragma unroll
            for (int k = 0; k < EDGE_DIM; k++) {
                float ea = eat[e * EDGE_DIM + k];
                v0 += sw1c[k * 64 + o0] * ea;
                v1 += sw1c[k * 64 + o0 + 1] * ea;
            }
            *reinterpret_cast<__half2*>(&z1h[e * Z1S + o0]) =
                __floats2half2_rn(fmaxf(v0, 0.f), fmaxf(v1, 0.f));
        }
        __syncthreads();

        // phase B: GEMM2 HMMA; epilogue -> z2h fp16 [e][k]
        {
            float acc[2][4];
            #pragma unroll
            for (int n = 0; n < 2; n++)
                #pragma unroll
                for (int c = 0; c < 4; c++) acc[n][c] = 0.f;
            #pragma unroll
            for (int kt = 0; kt < 4; kt++) {
                u32 a[4];
                u32 addr = z1base + ((eb + (lane & 15)) * Z1S + kt * 16 + (lane >> 4) * 8) * 2;
                ldsm_x4(a[0], a[1], a[2], a[3], addr);
                mma16816(acc[0], a, bf[kt][0]);
                mma16816(acc[1], a, bf[kt][1]);
            }
            int g = lane >> 2, t4 = lane & 3;
            #pragma unroll
            for (int nt2 = 0; nt2 < 2; nt2++) {
                int ob = oh + nt2 * 8 + t4 * 2;
                float b0 = sb2[ob], b1 = sb2[ob + 1];
                *reinterpret_cast<__half2*>(&z2h[(eb + g) * Z2S + ob]) =
                    __floats2half2_rn(fmaxf(acc[nt2][0] + b0, 0.f),
                                      fmaxf(acc[nt2][1] + b1, 0.f));
                *reinterpret_cast<__half2*>(&z2h[(eb + g + 8) * Z2S + ob]) =
                    __floats2half2_rn(fmaxf(acc[nt2][2] + b0, 0.f),
                                      fmaxf(acc[nt2][3] + b1, 0.f));
            }
        }
        __syncthreads();

        // phase C: GEMM3 HMMA (warps 0-3, one 16-edge tile each)
        if (wid < 4) {
            float c3[4] = {0.f, 0.f, 0.f, 0.f};
            int m0c = wid * 16;
            #pragma unroll
            for (int kt = 0; kt < 2; kt++) {
                u32 a[4];
                ldsm_x4(a[0], a[1], a[2], a[3],
                        z2base + ((m0c + (lane & 15)) * Z2S + kt * 16 + (lane >> 4) * 8) * 2);
                mma16816(c3, a, bf3[kt]);
            }
            int g = lane >> 2, t4 = lane & 3;
            if (t4 < 2) {
                int col = t4 * 2;
                float b0 = sb3[col], b1 = sb3[col + 1];
                int e0r = m0c + g;
                if (e0r < nE)
                    *reinterpret_cast<float2*>(&out[(size_t)(ebb + e0r) * DEC_OUT + col]) =
                        make_float2(c3[0] + b0, c3[1] + b1);
                int e1r = e0r + 8;
                if (e1r < nE)
                    *reinterpret_cast<float2*>(&out[(size_t)(ebb + e1r) * DEC_OUT + col]) =
                        make_float2(c3[2] + b0, c3[3] + b1);
            }
        }
    }
}

// ---------------- launch -----------------------------------------------------
extern "C" void kernel_launch(void* const* d_in, const int* in_sizes, int n_in,
                              void* d_out, int out_size) {
    const float* x     = (const float*)d_in[0];
    const int*   ei    = (const int*)d_in[1];
    const float* eattr = (const float*)d_in[2];
    const float* u     = (const float*)d_in[3];
    const float* W1    = (const float*)d_in[4];
    const float* as1   = (const float*)d_in[5];
    const float* ad1   = (const float*)d_in[6];
    const float* b1    = (const float*)d_in[7];
    const float* W2    = (const float*)d_in[8];
    const float* as2   = (const float*)d_in[9];
    const float* ad2   = (const float*)d_in[10];
    const float* b2    = (const float*)d_in[11];
    const float* dw1   = (const float*)d_in[12];
    const float* db1   = (const float*)d_in[13];
    const float* dw2   = (const float*)d_in[14];
    const float* db2   = (const float*)d_in[15];
    const float* dw3   = (const float*)d_in[16];
    const float* db3   = (const float*)d_in[17];
    float* out = (float*)d_out;

    int N = in_sizes[0] / IN_NODE;
    int M = in_sizes[1] / 2;
    if (N > NMAX || M > EMAX || N <= 0 || M <= 0) return;

    const int* srcp = ei;
    const int* dstp = ei + M;
    int nb = (N + 1023) / 1024;

    k_prep_all<<<65 + (N + 255) / 256, 256>>>(u, W1, dw2, W2, N);
    k_hist<<<(M + 255) / 256, 256>>>(dstp, M);
    k_scan1<<<nb, 1024>>>(N);
    k_scan3<<<(N + 255) / 256, 256>>>(nb, N, M);
    k_scatter<<<(M + 255) / 256, 256>>>(srcp, dstp, M);

    k_gemm1<<<(N + G1N - 1) / G1N, 128>>>(x, as1, ad1, N);
    k_agg<<<N, 128>>>(b1, 1, N);

    k_gemm2<<<(N + G2N - 1) / G2N, 256>>>(N);
    k_logits<<<(N + 3) / 4, 512>>>(as2, ad2, N);
    k_agg<<<N, 128>>>(b2, 0, N);

    k_pab<<<(N + 15) / 16, 256>>>(dw1, N);
    k_dec<<<1184, 256>>>(ei, eattr, dw1, db1, db2, dw3, db3, out, M);
}